// round 2
// baseline (speedup 1.0000x reference)
#include <cuda_runtime.h>
#include <math.h>

#define N_NODES 100000
#define N_EDGESC 1600000
#define NF 128
#define DIMS 64
#define NC 16
#define NREL 8
#define NP1 640   // layer1 cols: 512 rel + 64 root + 8 u(dst) + 8 v(src) + 48 pad
#define NP2 256   // layer2 cols: 128 rel + 16 root + 8 u + 8 v + 96 pad

// ---- scratch (static __device__ arrays; no allocation allowed) ----
__device__ float g_h1[(size_t)N_NODES * NP1];   // 256 MB
__device__ float g_x2[(size_t)N_NODES * DIMS];  // 25.6 MB
__device__ float g_h2[(size_t)N_NODES * NP2];   // 102 MB
__device__ float g_W1[NF * NP1];
__device__ float g_W2[DIMS * NP2];
__device__ int   g_rowptr[N_NODES + 1];
__device__ int   g_cnt[N_NODES];                // counts, then cursor
__device__ int   g_srcp[N_EDGESC];
__device__ int   g_etp[N_EDGESC];
__device__ float g_ewp[N_EDGESC];

// ---------------------------------------------------------------------------
// Weight prep: build fused weight matrices.
//   Wbig1[f][c]: c<512 -> W1[r=c/64][f][o=c%64]; 512..575 -> root1[f][c-512];
//                576..583 -> u[r]=W1[r]@att1[r,:64]; 584..591 -> v[r]=W1[r]@att1[r,64:]
//   Wbig2 analogous with 16-dim outputs.
// ---------------------------------------------------------------------------
__global__ void prep_kernel(const float* __restrict__ W1, const float* __restrict__ att1,
                            const float* __restrict__ root1,
                            const float* __restrict__ W2, const float* __restrict__ att2,
                            const float* __restrict__ root2) {
    int i = blockIdx.x * blockDim.x + threadIdx.x;
    if (i < NF * NP1) {
        int f = i / NP1, c = i % NP1;
        float v = 0.f;
        if (c < 512) {
            int r = c >> 6, o = c & 63;
            v = W1[r * NF * DIMS + f * DIMS + o];
        } else if (c < 576) {
            v = root1[f * DIMS + (c - 512)];
        } else if (c < 584) {
            int r = c - 576; float s = 0.f;
            for (int o = 0; o < DIMS; o++) s += W1[r * NF * DIMS + f * DIMS + o] * att1[r * 2 * DIMS + o];
            v = s;
        } else if (c < 592) {
            int r = c - 584; float s = 0.f;
            for (int o = 0; o < DIMS; o++) s += W1[r * NF * DIMS + f * DIMS + o] * att1[r * 2 * DIMS + DIMS + o];
            v = s;
        }
        g_W1[i] = v;
    } else {
        int j = i - NF * NP1;
        if (j < DIMS * NP2) {
            int f = j / NP2, c = j % NP2;
            float v = 0.f;
            if (c < 128) {
                int r = c >> 4, o = c & 15;
                v = W2[r * DIMS * NC + f * NC + o];
            } else if (c < 144) {
                v = root2[f * NC + (c - 128)];
            } else if (c < 152) {
                int r = c - 144; float s = 0.f;
                for (int o = 0; o < NC; o++) s += W2[r * DIMS * NC + f * NC + o] * att2[r * 2 * NC + o];
                v = s;
            } else if (c < 160) {
                int r = c - 152; float s = 0.f;
                for (int o = 0; o < NC; o++) s += W2[r * DIMS * NC + f * NC + o] * att2[r * 2 * NC + NC + o];
                v = s;
            }
            g_W2[j] = v;
        }
    }
}

__global__ void zero_kernel() {
    int i = blockIdx.x * blockDim.x + threadIdx.x;
    if (i < N_NODES) g_cnt[i] = 0;
}

__global__ void hist_kernel(const int* __restrict__ ei) {
    int e = blockIdx.x * blockDim.x + threadIdx.x;
    if (e < N_EDGESC) atomicAdd(&g_cnt[ei[N_EDGESC + e]], 1);
}

// single-block exclusive scan over 100K counts -> row_ptr, reset cursor
__global__ void scan_kernel() {
    __shared__ int sh[1024];
    int t = threadIdx.x;
    const int chunk = (N_NODES + 1023) / 1024;
    int start = t * chunk;
    int end = start + chunk; if (end > N_NODES) end = N_NODES;
    int s = 0;
    for (int i = start; i < end && start < N_NODES; i++) s += g_cnt[i];
    if (start >= N_NODES) s = 0;
    sh[t] = s; __syncthreads();
    for (int off = 1; off < 1024; off <<= 1) {
        int v = (t >= off) ? sh[t - off] : 0;
        __syncthreads();
        sh[t] += v;
        __syncthreads();
    }
    int off = sh[t] - s;  // exclusive prefix
    if (start < N_NODES) {
        for (int i = start; i < end; i++) {
            int c = g_cnt[i];
            g_rowptr[i] = off;
            g_cnt[i] = off;   // cursor for scatter
            off += c;
        }
    }
    if (t == 1023) g_rowptr[N_NODES] = sh[1023];
}

__global__ void scatter_kernel(const int* __restrict__ ei, const float* __restrict__ ew,
                               const int* __restrict__ ec) {
    int e = blockIdx.x * blockDim.x + threadIdx.x;
    if (e >= N_EDGESC) return;
    int d = ei[N_EDGESC + e];
    int p = atomicAdd(&g_cnt[d], 1);
    g_srcp[p] = ei[e];
    g_etp[p]  = ec[e];
    g_ewp[p]  = ew[e];
}

// ---------------------------------------------------------------------------
// FP32 SIMT GEMM: C[M,N] = A[M,K] @ B[K,N].  128x128 tile, BK=16, 8x8/thread.
// Templated on layer: LAYER==1 -> A=x (param), B=g_W1, C=g_h1, N=NP1, K=NF
//                     LAYER==2 -> A=g_x2,     B=g_W2, C=g_h2, N=NP2, K=DIMS
// All scratch referenced as __device__ globals directly (no symbol-address API).
// ---------------------------------------------------------------------------
template <int LAYER>
__global__ __launch_bounds__(256) void gemm_kernel(const float* __restrict__ x_in) {
    const int N = (LAYER == 1) ? NP1 : NP2;
    const int K = (LAYER == 1) ? NF : DIMS;
    const int M = N_NODES;
    const float* __restrict__ A = (LAYER == 1) ? x_in : g_x2;
    const float* __restrict__ B = (LAYER == 1) ? g_W1 : g_W2;
    float* __restrict__ C       = (LAYER == 1) ? g_h1 : g_h2;

    __shared__ float As[16][128];
    __shared__ float Bs[16][128];
    int tid = threadIdx.x;
    int row0 = blockIdx.y * 128;
    int col0 = blockIdx.x * 128;
    int tm = (tid >> 4) << 3;
    int tn = (tid & 15) << 3;
    float acc[8][8];
#pragma unroll
    for (int i = 0; i < 8; i++)
#pragma unroll
        for (int j = 0; j < 8; j++) acc[i][j] = 0.f;

    for (int kt = 0; kt < K; kt += 16) {
#pragma unroll
        for (int l = 0; l < 2; l++) {
            int f4 = tid + l * 256;
            // A: 128 rows x 16 cols (transpose into As[k][m])
            int r = f4 >> 2, c4 = f4 & 3;
            float4 a = make_float4(0.f, 0.f, 0.f, 0.f);
            int gr = row0 + r;
            if (gr < M) a = *(const float4*)&A[(size_t)gr * K + kt + c4 * 4];
            As[c4 * 4 + 0][r] = a.x;
            As[c4 * 4 + 1][r] = a.y;
            As[c4 * 4 + 2][r] = a.z;
            As[c4 * 4 + 3][r] = a.w;
            // B: 16 rows x 128 cols
            int rb = f4 >> 5, cb = f4 & 31;
            float4 b = *(const float4*)&B[(size_t)(kt + rb) * N + col0 + cb * 4];
            *(float4*)&Bs[rb][cb * 4] = b;
        }
        __syncthreads();
#pragma unroll
        for (int k = 0; k < 16; k++) {
            float a[8], b[8];
            *(float4*)&a[0] = *(const float4*)&As[k][tm];
            *(float4*)&a[4] = *(const float4*)&As[k][tm + 4];
            *(float4*)&b[0] = *(const float4*)&Bs[k][tn];
            *(float4*)&b[4] = *(const float4*)&Bs[k][tn + 4];
#pragma unroll
            for (int i = 0; i < 8; i++)
#pragma unroll
                for (int j = 0; j < 8; j++) acc[i][j] += a[i] * b[j];
        }
        __syncthreads();
    }
#pragma unroll
    for (int i = 0; i < 8; i++) {
        int gr = row0 + tm + i;
        if (gr < M) {
            float4 v0 = make_float4(acc[i][0], acc[i][1], acc[i][2], acc[i][3]);
            float4 v1 = make_float4(acc[i][4], acc[i][5], acc[i][6], acc[i][7]);
            *(float4*)&C[(size_t)gr * N + col0 + tn]     = v0;
            *(float4*)&C[(size_t)gr * N + col0 + tn + 4] = v1;
        }
    }
}

// ---------------------------------------------------------------------------
// Edge pass layer 1: warp per destination node. Pass A: max of leaky-relu logit.
// Pass B: accumulate sum(exp) and sum(ew*exp*h_src) (64-dim, 2 floats/lane).
// ---------------------------------------------------------------------------
__global__ __launch_bounds__(256) void edge1_kernel(const float* __restrict__ b1) {
    int w = (blockIdx.x * blockDim.x + threadIdx.x) >> 5;
    int lane = threadIdx.x & 31;
    if (w >= N_NODES) return;
    int rb = g_rowptr[w], re = g_rowptr[w + 1];
    size_t dbase = (size_t)w * NP1;

    float m = -3.4e38f;
    for (int i = rb + lane; i < re; i += 32) {
        int s = g_srcp[i], et = g_etp[i];
        float e = g_h1[dbase + 576 + et] + g_h1[(size_t)s * NP1 + 584 + et];
        e = e >= 0.f ? e : 0.2f * e;
        m = fmaxf(m, e);
    }
#pragma unroll
    for (int o = 16; o > 0; o >>= 1) m = fmaxf(m, __shfl_xor_sync(0xffffffffu, m, o));

    float acc0 = 0.f, acc1 = 0.f, sum = 0.f;
    int f2 = lane * 2;
    for (int i = rb; i < re; i++) {
        int s = g_srcp[i], et = g_etp[i];
        float wgt = g_ewp[i];
        float e = g_h1[dbase + 576 + et] + g_h1[(size_t)s * NP1 + 584 + et];
        e = e >= 0.f ? e : 0.2f * e;
        float ex = __expf(e - m);
        sum += ex;
        float c = wgt * ex;
        float2 hv = *(const float2*)&g_h1[(size_t)s * NP1 + et * DIMS + f2];
        acc0 += c * hv.x;
        acc1 += c * hv.y;
    }
    float inv = 1.f / (sum + 1e-16f);
    float o0 = acc0 * inv + g_h1[dbase + 512 + f2]     + b1[f2];
    float o1 = acc1 * inv + g_h1[dbase + 512 + f2 + 1] + b1[f2 + 1];
    o0 = fmaxf(o0, 0.f);
    o1 = fmaxf(o1, 0.f);
    *(float2*)&g_x2[(size_t)w * DIMS + f2] = make_float2(o0, o1);
}

// ---------------------------------------------------------------------------
// Edge pass layer 2: warp per dst; halves of the warp process alternate edges
// (16-dim features). Finish with in-warp log_softmax; write both outputs.
// ---------------------------------------------------------------------------
__global__ __launch_bounds__(256) void edge2_kernel(const float* __restrict__ b2,
                                                    float* __restrict__ out,
                                                    int write_logits) {
    int d = (blockIdx.x * blockDim.x + threadIdx.x) >> 5;
    int lane = threadIdx.x & 31;
    if (d >= N_NODES) return;
    int rb = g_rowptr[d], re = g_rowptr[d + 1];
    size_t dbase = (size_t)d * NP2;

    float m = -3.4e38f;
    for (int i = rb + lane; i < re; i += 32) {
        int s = g_srcp[i], et = g_etp[i];
        float e = g_h2[dbase + 144 + et] + g_h2[(size_t)s * NP2 + 152 + et];
        e = e >= 0.f ? e : 0.2f * e;
        m = fmaxf(m, e);
    }
#pragma unroll
    for (int o = 16; o > 0; o >>= 1) m = fmaxf(m, __shfl_xor_sync(0xffffffffu, m, o));

    int hw = lane >> 4, f = lane & 15;
    float acc = 0.f, sum = 0.f;
    for (int i = rb + hw; i < re; i += 2) {
        int s = g_srcp[i], et = g_etp[i];
        float wgt = g_ewp[i];
        float e = g_h2[dbase + 144 + et] + g_h2[(size_t)s * NP2 + 152 + et];
        e = e >= 0.f ? e : 0.2f * e;
        float ex = __expf(e - m);
        sum += ex;
        acc += wgt * ex * g_h2[(size_t)s * NP2 + et * NC + f];
    }
    acc += __shfl_xor_sync(0xffffffffu, acc, 16);
    sum += __shfl_xor_sync(0xffffffffu, sum, 16);

    float logit = acc / (sum + 1e-16f) + g_h2[dbase + 128 + f] + b2[f];

    float mx = logit;
#pragma unroll
    for (int o = 8; o > 0; o >>= 1) mx = fmaxf(mx, __shfl_xor_sync(0xffffffffu, mx, o));
    float ex = __expf(logit - mx);
    float ss = ex;
#pragma unroll
    for (int o = 8; o > 0; o >>= 1) ss += __shfl_xor_sync(0xffffffffu, ss, o);
    float ls = logit - mx - __logf(ss);

    if (lane < 16) {
        out[(size_t)d * NC + f] = ls;
        if (write_logits) out[(size_t)N_NODES * NC + (size_t)d * NC + f] = logit;
    }
}

// ---------------------------------------------------------------------------
extern "C" void kernel_launch(void* const* d_in, const int* in_sizes, int n_in,
                              void* d_out, int out_size) {
    const float* x     = (const float*)d_in[0];
    const int*   ei    = (const int*)d_in[1];
    const float* ew    = (const float*)d_in[2];
    const int*   ec    = (const int*)d_in[3];
    const float* W1    = (const float*)d_in[4];
    const float* att1  = (const float*)d_in[5];
    const float* root1 = (const float*)d_in[6];
    const float* b1    = (const float*)d_in[7];
    const float* W2    = (const float*)d_in[8];
    const float* att2  = (const float*)d_in[9];
    const float* root2 = (const float*)d_in[10];
    const float* b2    = (const float*)d_in[11];
    float* out = (float*)d_out;
    int write_logits = (out_size >= 2 * N_NODES * NC);

    // 1. fused weights + CSR build
    prep_kernel<<<(NF * NP1 + DIMS * NP2 + 255) / 256, 256>>>(W1, att1, root1, W2, att2, root2);
    zero_kernel<<<(N_NODES + 255) / 256, 256>>>();
    hist_kernel<<<(N_EDGESC + 255) / 256, 256>>>(ei);
    scan_kernel<<<1, 1024>>>();
    scatter_kernel<<<(N_EDGESC + 255) / 256, 256>>>(ei, ew, ec);

    // 2. layer-1 fused GEMM: [100K,128] @ [128,640]
    {
        dim3 grid(NP1 / 128, (N_NODES + 127) / 128);
        gemm_kernel<1><<<grid, 256>>>(x);
    }
    // 3. layer-1 edge aggregation -> x2 (with relu)
    edge1_kernel<<<(N_NODES * 32 + 255) / 256, 256>>>(b1);

    // 4. layer-2 fused GEMM: [100K,64] @ [64,256]
    {
        dim3 grid(NP2 / 128, (N_NODES + 127) / 128);
        gemm_kernel<2><<<grid, 256>>>(nullptr);
    }
    // 5. layer-2 edge aggregation + log_softmax -> out
    edge2_kernel<<<(N_NODES * 32 + 255) / 256, 256>>>(b2, out, write_logits);
}

// round 3
// speedup vs baseline: 1.7657x; 1.7657x over previous
#include <cuda_runtime.h>
#include <math.h>
#include <stdint.h>

#define N_NODES 100000
#define N_EDGESC 1600000
#define NF 128
#define DIMS 64
#define NC 16
#define NREL 8
#define NP1 640   // layer1 cols: 512 rel + 64 root + 8 u(dst) + 8 v(src) + 48 pad
#define NP2 256   // layer2 cols: 128 rel + 16 root + 8 u + 8 v + 96 pad

#define SCAN_CHUNK 1024
#define SCAN_NBLK 98   // 98*1024 = 100352 >= 100000

// ---- scratch (static __device__ arrays; no allocation allowed) ----
__device__ float g_h1[(size_t)N_NODES * NP1];   // 256 MB
__device__ float g_x2[(size_t)N_NODES * DIMS];  // 25.6 MB
__device__ float g_h2[(size_t)N_NODES * NP2];   // 102 MB
__device__ float g_W1[NF * NP1];
__device__ float g_W2[DIMS * NP2];
__device__ int   g_rowptr[N_NODES + 1];
__device__ int   g_cnt[N_NODES];                // counts, then cursor
__device__ int   g_bsum[SCAN_NBLK];
__device__ int   g_srcp[N_EDGESC];
__device__ int   g_etp[N_EDGESC];
__device__ float g_ewp[N_EDGESC];

__device__ __forceinline__ uint32_t f2tf(float f) {
    uint32_t u;
    asm("cvt.rna.tf32.f32 %0, %1;" : "=r"(u) : "f"(f));
    return u;
}

// ---------------------------------------------------------------------------
// Weight prep: build fused weight matrices.
//   Wbig1[f][c]: c<512 -> W1[r=c/64][f][o=c%64]; 512..575 -> root1[f][c-512];
//                576..583 -> u[r]=W1[r]@att1[r,:64]; 584..591 -> v[r]=W1[r]@att1[r,64:]
//   Wbig2 analogous with 16-dim outputs.
// ---------------------------------------------------------------------------
__global__ void prep_kernel(const float* __restrict__ W1, const float* __restrict__ att1,
                            const float* __restrict__ root1,
                            const float* __restrict__ W2, const float* __restrict__ att2,
                            const float* __restrict__ root2) {
    int i = blockIdx.x * blockDim.x + threadIdx.x;
    if (i < NF * NP1) {
        int f = i / NP1, c = i % NP1;
        float v = 0.f;
        if (c < 512) {
            int r = c >> 6, o = c & 63;
            v = W1[r * NF * DIMS + f * DIMS + o];
        } else if (c < 576) {
            v = root1[f * DIMS + (c - 512)];
        } else if (c < 584) {
            int r = c - 576; float s = 0.f;
            for (int o = 0; o < DIMS; o++) s += W1[r * NF * DIMS + f * DIMS + o] * att1[r * 2 * DIMS + o];
            v = s;
        } else if (c < 592) {
            int r = c - 584; float s = 0.f;
            for (int o = 0; o < DIMS; o++) s += W1[r * NF * DIMS + f * DIMS + o] * att1[r * 2 * DIMS + DIMS + o];
            v = s;
        }
        g_W1[i] = v;
    } else {
        int j = i - NF * NP1;
        if (j < DIMS * NP2) {
            int f = j / NP2, c = j % NP2;
            float v = 0.f;
            if (c < 128) {
                int r = c >> 4, o = c & 15;
                v = W2[r * DIMS * NC + f * NC + o];
            } else if (c < 144) {
                v = root2[f * NC + (c - 128)];
            } else if (c < 152) {
                int r = c - 144; float s = 0.f;
                for (int o = 0; o < NC; o++) s += W2[r * DIMS * NC + f * NC + o] * att2[r * 2 * NC + o];
                v = s;
            } else if (c < 160) {
                int r = c - 152; float s = 0.f;
                for (int o = 0; o < NC; o++) s += W2[r * DIMS * NC + f * NC + o] * att2[r * 2 * NC + NC + o];
                v = s;
            }
            g_W2[j] = v;
        }
    }
}

__global__ void zero_kernel() {
    int i = blockIdx.x * blockDim.x + threadIdx.x;
    if (i < N_NODES) g_cnt[i] = 0;
}

__global__ void hist_kernel(const int* __restrict__ ei) {
    int e = blockIdx.x * blockDim.x + threadIdx.x;
    if (e < N_EDGESC) atomicAdd(&g_cnt[ei[N_EDGESC + e]], 1);
}

// ---- hierarchical scan: blocksums -> scan blocksums -> per-block rescan ----
__global__ __launch_bounds__(256) void blocksum_kernel() {
    __shared__ int sh[256];
    int b = blockIdx.x, t = threadIdx.x;
    int base = b * SCAN_CHUNK + t * 4;
    int s = 0;
#pragma unroll
    for (int q = 0; q < 4; q++) {
        int i = base + q;
        if (i < N_NODES) s += g_cnt[i];
    }
    sh[t] = s; __syncthreads();
    for (int off = 128; off > 0; off >>= 1) {
        if (t < off) sh[t] += sh[t + off];
        __syncthreads();
    }
    if (t == 0) g_bsum[b] = sh[0];
}

__global__ void scanb_kernel() {
    __shared__ int sh[128];
    int t = threadIdx.x;
    int v = (t < SCAN_NBLK) ? g_bsum[t] : 0;
    sh[t] = v; __syncthreads();
    for (int off = 1; off < 128; off <<= 1) {
        int x = (t >= off) ? sh[t - off] : 0;
        __syncthreads();
        sh[t] += x;
        __syncthreads();
    }
    if (t < SCAN_NBLK) g_bsum[t] = sh[t] - v;  // exclusive
}

__global__ __launch_bounds__(256) void rowptr_kernel() {
    __shared__ int sh[256];
    int b = blockIdx.x, t = threadIdx.x;
    int base = b * SCAN_CHUNK + t * 4;
    int c[4];
#pragma unroll
    for (int q = 0; q < 4; q++) {
        int i = base + q;
        c[q] = (i < N_NODES) ? g_cnt[i] : 0;
    }
    int tot = c[0] + c[1] + c[2] + c[3];
    sh[t] = tot; __syncthreads();
    for (int off = 1; off < 256; off <<= 1) {
        int x = (t >= off) ? sh[t - off] : 0;
        __syncthreads();
        sh[t] += x;
        __syncthreads();
    }
    int off = g_bsum[b] + sh[t] - tot;  // exclusive prefix for this thread
#pragma unroll
    for (int q = 0; q < 4; q++) {
        int i = base + q;
        if (i < N_NODES) {
            g_rowptr[i] = off;
            g_cnt[i] = off;   // cursor for scatter
            off += c[q];
        }
    }
    if (b == 0 && t == 0) g_rowptr[N_NODES] = N_EDGESC;
}

__global__ void scatter_kernel(const int* __restrict__ ei, const float* __restrict__ ew,
                               const int* __restrict__ ec) {
    int e = blockIdx.x * blockDim.x + threadIdx.x;
    if (e >= N_EDGESC) return;
    int d = ei[N_EDGESC + e];
    int p = atomicAdd(&g_cnt[d], 1);
    g_srcp[p] = ei[e];
    g_etp[p]  = ec[e];
    g_ewp[p]  = ew[e];
}

// ---------------------------------------------------------------------------
// TF32 tensor-core GEMM: C[M,N] = A[M,K] @ B[K,N].
// Block tile 128x128, BK=32, 8 warps (2x4), warp tile 64x32.
// mma.sync.aligned.m16n8k8.row.col.f32.tf32.tf32.f32.
// Operands converted to tf32 (cvt.rna) during the smem fill.
// smem rows padded to 136 words -> fragment LDS is bank-conflict-free.
// ---------------------------------------------------------------------------
#define LDSW 136

template <int LAYER>
__global__ __launch_bounds__(256, 2) void gemm_tf32(const float* __restrict__ x_in) {
    constexpr int K = (LAYER == 1) ? NF : DIMS;
    constexpr int N = (LAYER == 1) ? NP1 : NP2;
    const float* __restrict__ A = (LAYER == 1) ? x_in : g_x2;
    const float* __restrict__ Bw = (LAYER == 1) ? g_W1 : g_W2;
    float* __restrict__ C        = (LAYER == 1) ? g_h1 : g_h2;

    __shared__ uint32_t As[32 * LDSW];
    __shared__ uint32_t Bs[32 * LDSW];

    int tid = threadIdx.x;
    int lane = tid & 31, wid = tid >> 5;
    int row0 = blockIdx.y * 128, col0 = blockIdx.x * 128;
    int wm = wid >> 2, wn = wid & 3;          // warp grid 2 (m) x 4 (n)
    int gq = lane >> 2, tq = lane & 3;        // fragment coords

    float c[4][4][4];
#pragma unroll
    for (int a = 0; a < 4; a++)
#pragma unroll
        for (int b = 0; b < 4; b++)
#pragma unroll
            for (int d = 0; d < 4; d++) c[a][b][d] = 0.f;

    for (int kt = 0; kt < K; kt += 32) {
        // A: 128 rows x 32 k -> As[k][m] (transposed), tf32-converted
#pragma unroll
        for (int p = 0; p < 4; p++) {
            int idx = tid + p * 256;
            int r = idx >> 3, kq = idx & 7;
            int gr = row0 + r;
            float4 v = make_float4(0.f, 0.f, 0.f, 0.f);
            if (gr < N_NODES) v = *(const float4*)&A[(size_t)gr * K + kt + kq * 4];
            As[(kq * 4 + 0) * LDSW + r] = f2tf(v.x);
            As[(kq * 4 + 1) * LDSW + r] = f2tf(v.y);
            As[(kq * 4 + 2) * LDSW + r] = f2tf(v.z);
            As[(kq * 4 + 3) * LDSW + r] = f2tf(v.w);
        }
        // B: 32 k x 128 cols -> Bs[k][n], tf32-converted
#pragma unroll
        for (int p = 0; p < 4; p++) {
            int idx = tid + p * 256;
            int kk = idx >> 5, nq = idx & 31;
            float4 v = *(const float4*)&Bw[(size_t)(kt + kk) * N + col0 + nq * 4];
            uint32_t* dst = &Bs[kk * LDSW + nq * 4];
            dst[0] = f2tf(v.x); dst[1] = f2tf(v.y); dst[2] = f2tf(v.z); dst[3] = f2tf(v.w);
        }
        __syncthreads();

#pragma unroll
        for (int k8 = 0; k8 < 32; k8 += 8) {
            uint32_t af[4][4], bf[4][2];
#pragma unroll
            for (int mi = 0; mi < 4; mi++) {
                int R = wm * 64 + mi * 16;
                af[mi][0] = As[(k8 + tq) * LDSW + R + gq];
                af[mi][1] = As[(k8 + tq) * LDSW + R + gq + 8];
                af[mi][2] = As[(k8 + tq + 4) * LDSW + R + gq];
                af[mi][3] = As[(k8 + tq + 4) * LDSW + R + gq + 8];
            }
#pragma unroll
            for (int nj = 0; nj < 4; nj++) {
                int Cb = wn * 32 + nj * 8;
                bf[nj][0] = Bs[(k8 + tq) * LDSW + Cb + gq];
                bf[nj][1] = Bs[(k8 + tq + 4) * LDSW + Cb + gq];
            }
#pragma unroll
            for (int mi = 0; mi < 4; mi++)
#pragma unroll
                for (int nj = 0; nj < 4; nj++) {
                    asm volatile(
                        "mma.sync.aligned.m16n8k8.row.col.f32.tf32.tf32.f32 "
                        "{%0,%1,%2,%3}, {%4,%5,%6,%7}, {%8,%9}, {%0,%1,%2,%3};\n"
                        : "+f"(c[mi][nj][0]), "+f"(c[mi][nj][1]),
                          "+f"(c[mi][nj][2]), "+f"(c[mi][nj][3])
                        : "r"(af[mi][0]), "r"(af[mi][1]), "r"(af[mi][2]), "r"(af[mi][3]),
                          "r"(bf[nj][0]), "r"(bf[nj][1]));
                }
        }
        __syncthreads();
    }

#pragma unroll
    for (int mi = 0; mi < 4; mi++) {
#pragma unroll
        for (int nj = 0; nj < 4; nj++) {
            int row = row0 + wm * 64 + mi * 16 + gq;
            int col = col0 + wn * 32 + nj * 8 + 2 * tq;
            if (row < N_NODES)
                *(float2*)&C[(size_t)row * N + col] = make_float2(c[mi][nj][0], c[mi][nj][1]);
            if (row + 8 < N_NODES)
                *(float2*)&C[(size_t)(row + 8) * N + col] = make_float2(c[mi][nj][2], c[mi][nj][3]);
        }
    }
}

// ---------------------------------------------------------------------------
// Edge pass layer 1: warp per destination node. Pass A: max of leaky-relu logit.
// Pass B: accumulate sum(exp) and sum(ew*exp*h_src) (64-dim, 2 floats/lane).
// ---------------------------------------------------------------------------
__global__ __launch_bounds__(256) void edge1_kernel(const float* __restrict__ b1) {
    int w = (blockIdx.x * blockDim.x + threadIdx.x) >> 5;
    int lane = threadIdx.x & 31;
    if (w >= N_NODES) return;
    int rb = g_rowptr[w], re = g_rowptr[w + 1];
    size_t dbase = (size_t)w * NP1;

    float m = -3.4e38f;
    for (int i = rb + lane; i < re; i += 32) {
        int s = g_srcp[i], et = g_etp[i];
        float e = g_h1[dbase + 576 + et] + g_h1[(size_t)s * NP1 + 584 + et];
        e = e >= 0.f ? e : 0.2f * e;
        m = fmaxf(m, e);
    }
#pragma unroll
    for (int o = 16; o > 0; o >>= 1) m = fmaxf(m, __shfl_xor_sync(0xffffffffu, m, o));

    float acc0 = 0.f, acc1 = 0.f, sum = 0.f;
    int f2 = lane * 2;
    for (int i = rb; i < re; i++) {
        int s = g_srcp[i], et = g_etp[i];
        float wgt = g_ewp[i];
        float e = g_h1[dbase + 576 + et] + g_h1[(size_t)s * NP1 + 584 + et];
        e = e >= 0.f ? e : 0.2f * e;
        float ex = __expf(e - m);
        sum += ex;
        float cc = wgt * ex;
        float2 hv = *(const float2*)&g_h1[(size_t)s * NP1 + et * DIMS + f2];
        acc0 += cc * hv.x;
        acc1 += cc * hv.y;
    }
    float inv = 1.f / (sum + 1e-16f);
    float o0 = acc0 * inv + g_h1[dbase + 512 + f2]     + b1[f2];
    float o1 = acc1 * inv + g_h1[dbase + 512 + f2 + 1] + b1[f2 + 1];
    o0 = fmaxf(o0, 0.f);
    o1 = fmaxf(o1, 0.f);
    *(float2*)&g_x2[(size_t)w * DIMS + f2] = make_float2(o0, o1);
}

// ---------------------------------------------------------------------------
// Edge pass layer 2: warp per dst; halves of the warp process alternate edges
// (16-dim features). Finish with in-warp log_softmax; write both outputs.
// ---------------------------------------------------------------------------
__global__ __launch_bounds__(256) void edge2_kernel(const float* __restrict__ b2,
                                                    float* __restrict__ out,
                                                    int write_logits) {
    int d = (blockIdx.x * blockDim.x + threadIdx.x) >> 5;
    int lane = threadIdx.x & 31;
    if (d >= N_NODES) return;
    int rb = g_rowptr[d], re = g_rowptr[d + 1];
    size_t dbase = (size_t)d * NP2;

    float m = -3.4e38f;
    for (int i = rb + lane; i < re; i += 32) {
        int s = g_srcp[i], et = g_etp[i];
        float e = g_h2[dbase + 144 + et] + g_h2[(size_t)s * NP2 + 152 + et];
        e = e >= 0.f ? e : 0.2f * e;
        m = fmaxf(m, e);
    }
#pragma unroll
    for (int o = 16; o > 0; o >>= 1) m = fmaxf(m, __shfl_xor_sync(0xffffffffu, m, o));

    int hw = lane >> 4, f = lane & 15;
    float acc = 0.f, sum = 0.f;
    for (int i = rb + hw; i < re; i += 2) {
        int s = g_srcp[i], et = g_etp[i];
        float wgt = g_ewp[i];
        float e = g_h2[dbase + 144 + et] + g_h2[(size_t)s * NP2 + 152 + et];
        e = e >= 0.f ? e : 0.2f * e;
        float ex = __expf(e - m);
        sum += ex;
        acc += wgt * ex * g_h2[(size_t)s * NP2 + et * NC + f];
    }
    acc += __shfl_xor_sync(0xffffffffu, acc, 16);
    sum += __shfl_xor_sync(0xffffffffu, sum, 16);

    float logit = acc / (sum + 1e-16f) + g_h2[dbase + 128 + f] + b2[f];

    float mx = logit;
#pragma unroll
    for (int o = 8; o > 0; o >>= 1) mx = fmaxf(mx, __shfl_xor_sync(0xffffffffu, mx, o));
    float ex = __expf(logit - mx);
    float ss = ex;
#pragma unroll
    for (int o = 8; o > 0; o >>= 1) ss += __shfl_xor_sync(0xffffffffu, ss, o);
    float ls = logit - mx - __logf(ss);

    if (lane < 16) {
        out[(size_t)d * NC + f] = ls;
        if (write_logits) out[(size_t)N_NODES * NC + (size_t)d * NC + f] = logit;
    }
}

// ---------------------------------------------------------------------------
extern "C" void kernel_launch(void* const* d_in, const int* in_sizes, int n_in,
                              void* d_out, int out_size) {
    const float* x     = (const float*)d_in[0];
    const int*   ei    = (const int*)d_in[1];
    const float* ew    = (const float*)d_in[2];
    const int*   ec    = (const int*)d_in[3];
    const float* W1    = (const float*)d_in[4];
    const float* att1  = (const float*)d_in[5];
    const float* root1 = (const float*)d_in[6];
    const float* b1    = (const float*)d_in[7];
    const float* W2    = (const float*)d_in[8];
    const float* att2  = (const float*)d_in[9];
    const float* root2 = (const float*)d_in[10];
    const float* b2    = (const float*)d_in[11];
    float* out = (float*)d_out;
    int write_logits = (out_size >= 2 * N_NODES * NC);

    // 1. fused weights + CSR build (hierarchical scan)
    prep_kernel<<<(NF * NP1 + DIMS * NP2 + 255) / 256, 256>>>(W1, att1, root1, W2, att2, root2);
    zero_kernel<<<(N_NODES + 255) / 256, 256>>>();
    hist_kernel<<<(N_EDGESC + 255) / 256, 256>>>(ei);
    blocksum_kernel<<<SCAN_NBLK, 256>>>();
    scanb_kernel<<<1, 128>>>();
    rowptr_kernel<<<SCAN_NBLK, 256>>>();
    scatter_kernel<<<(N_EDGESC + 255) / 256, 256>>>(ei, ew, ec);

    // 2. layer-1 fused GEMM (tf32 tensor cores): [100K,128] @ [128,640]
    {
        dim3 grid(NP1 / 128, (N_NODES + 127) / 128);
        gemm_tf32<1><<<grid, 256>>>(x);
    }
    // 3. layer-1 edge aggregation -> x2 (with relu)
    edge1_kernel<<<(N_NODES * 32 + 255) / 256, 256>>>(b1);

    // 4. layer-2 fused GEMM (tf32): [100K,64] @ [64,256]
    {
        dim3 grid(NP2 / 128, (N_NODES + 127) / 128);
        gemm_tf32<2><<<grid, 256>>>(nullptr);
    }
    // 5. layer-2 edge aggregation + log_softmax -> out
    edge2_kernel<<<(N_NODES * 32 + 255) / 256, 256>>>(b2, out, write_logits);
}

// round 4
// speedup vs baseline: 1.9675x; 1.1143x over previous
#include <cuda_runtime.h>
#include <math.h>
#include <stdint.h>

#define N_NODES 100000
#define N_EDGESC 1600000
#define NF 128
#define DIMS 64
#define NC 16
#define NREL 8
#define NP1 640   // layer1 cols: 512 rel + 64 root + 8 u(dst) + 8 v(src) + 48 pad
#define NP2 256   // layer2 cols: 128 rel + 16 root + 8 u + 8 v + 96 pad

#define SCAN_CHUNK 1024
#define SCAN_NBLK 98   // 98*1024 = 100352 >= 100000

// ---- scratch (static __device__ arrays; no allocation allowed) ----
__device__ float g_h1[(size_t)N_NODES * NP1];   // 256 MB
__device__ float g_x2[(size_t)N_NODES * DIMS];  // 25.6 MB
__device__ float g_h2[(size_t)N_NODES * NP2];   // 102 MB
__device__ float g_W1[NF * NP1];
__device__ float g_W2[DIMS * NP2];
__device__ int   g_rowptr[N_NODES + 1];
__device__ int   g_cnt[N_NODES];                // counts, then cursor
__device__ int   g_bsum[SCAN_NBLK];
__device__ int4  g_edge[N_EDGESC];              // {src, et, ew_bits, dst} CSR-ordered
__device__ float g_e[N_EDGESC];                 // leaky-relu attention logits

__device__ __forceinline__ uint32_t f2tf(float f) {
    uint32_t u;
    asm("cvt.rna.tf32.f32 %0, %1;" : "=r"(u) : "f"(f));
    return u;
}

// ---------------------------------------------------------------------------
// Weight prep: build fused weight matrices.
//   Wbig1[f][c]: c<512 -> W1[r=c/64][f][o=c%64]; 512..575 -> root1[f][c-512];
//                576..583 -> u[r]=W1[r]@att1[r,:64]; 584..591 -> v[r]=W1[r]@att1[r,64:]
//   Wbig2 analogous with 16-dim outputs.
// ---------------------------------------------------------------------------
__global__ void prep_kernel(const float* __restrict__ W1, const float* __restrict__ att1,
                            const float* __restrict__ root1,
                            const float* __restrict__ W2, const float* __restrict__ att2,
                            const float* __restrict__ root2) {
    int i = blockIdx.x * blockDim.x + threadIdx.x;
    if (i < NF * NP1) {
        int f = i / NP1, c = i % NP1;
        float v = 0.f;
        if (c < 512) {
            int r = c >> 6, o = c & 63;
            v = W1[r * NF * DIMS + f * DIMS + o];
        } else if (c < 576) {
            v = root1[f * DIMS + (c - 512)];
        } else if (c < 584) {
            int r = c - 576; float s = 0.f;
            for (int o = 0; o < DIMS; o++) s += W1[r * NF * DIMS + f * DIMS + o] * att1[r * 2 * DIMS + o];
            v = s;
        } else if (c < 592) {
            int r = c - 584; float s = 0.f;
            for (int o = 0; o < DIMS; o++) s += W1[r * NF * DIMS + f * DIMS + o] * att1[r * 2 * DIMS + DIMS + o];
            v = s;
        }
        g_W1[i] = v;
    } else {
        int j = i - NF * NP1;
        if (j < DIMS * NP2) {
            int f = j / NP2, c = j % NP2;
            float v = 0.f;
            if (c < 128) {
                int r = c >> 4, o = c & 15;
                v = W2[r * DIMS * NC + f * NC + o];
            } else if (c < 144) {
                v = root2[f * NC + (c - 128)];
            } else if (c < 152) {
                int r = c - 144; float s = 0.f;
                for (int o = 0; o < NC; o++) s += W2[r * DIMS * NC + f * NC + o] * att2[r * 2 * NC + o];
                v = s;
            } else if (c < 160) {
                int r = c - 152; float s = 0.f;
                for (int o = 0; o < NC; o++) s += W2[r * DIMS * NC + f * NC + o] * att2[r * 2 * NC + NC + o];
                v = s;
            }
            g_W2[j] = v;
        }
    }
}

__global__ void zero_kernel() {
    int i = blockIdx.x * blockDim.x + threadIdx.x;
    if (i < N_NODES) g_cnt[i] = 0;
}

__global__ void hist_kernel(const int* __restrict__ ei) {
    int e = blockIdx.x * blockDim.x + threadIdx.x;
    if (e < N_EDGESC) atomicAdd(&g_cnt[ei[N_EDGESC + e]], 1);
}

// ---- hierarchical scan: blocksums -> scan blocksums -> per-block rescan ----
__global__ __launch_bounds__(256) void blocksum_kernel() {
    __shared__ int sh[256];
    int b = blockIdx.x, t = threadIdx.x;
    int base = b * SCAN_CHUNK + t * 4;
    int s = 0;
#pragma unroll
    for (int q = 0; q < 4; q++) {
        int i = base + q;
        if (i < N_NODES) s += g_cnt[i];
    }
    sh[t] = s; __syncthreads();
    for (int off = 128; off > 0; off >>= 1) {
        if (t < off) sh[t] += sh[t + off];
        __syncthreads();
    }
    if (t == 0) g_bsum[b] = sh[0];
}

__global__ void scanb_kernel() {
    __shared__ int sh[128];
    int t = threadIdx.x;
    int v = (t < SCAN_NBLK) ? g_bsum[t] : 0;
    sh[t] = v; __syncthreads();
    for (int off = 1; off < 128; off <<= 1) {
        int x = (t >= off) ? sh[t - off] : 0;
        __syncthreads();
        sh[t] += x;
        __syncthreads();
    }
    if (t < SCAN_NBLK) g_bsum[t] = sh[t] - v;  // exclusive
}

__global__ __launch_bounds__(256) void rowptr_kernel() {
    __shared__ int sh[256];
    int b = blockIdx.x, t = threadIdx.x;
    int base = b * SCAN_CHUNK + t * 4;
    int c[4];
#pragma unroll
    for (int q = 0; q < 4; q++) {
        int i = base + q;
        c[q] = (i < N_NODES) ? g_cnt[i] : 0;
    }
    int tot = c[0] + c[1] + c[2] + c[3];
    sh[t] = tot; __syncthreads();
    for (int off = 1; off < 256; off <<= 1) {
        int x = (t >= off) ? sh[t - off] : 0;
        __syncthreads();
        sh[t] += x;
        __syncthreads();
    }
    int off = g_bsum[b] + sh[t] - tot;  // exclusive prefix for this thread
#pragma unroll
    for (int q = 0; q < 4; q++) {
        int i = base + q;
        if (i < N_NODES) {
            g_rowptr[i] = off;
            g_cnt[i] = off;   // cursor for scatter
            off += c[q];
        }
    }
    if (b == 0 && t == 0) g_rowptr[N_NODES] = N_EDGESC;
}

// single int4 scatter per edge (1 sector instead of 3)
__global__ void scatter_kernel(const int* __restrict__ ei, const float* __restrict__ ew,
                               const int* __restrict__ ec) {
    int e = blockIdx.x * blockDim.x + threadIdx.x;
    if (e >= N_EDGESC) return;
    int d = ei[N_EDGESC + e];
    int p = atomicAdd(&g_cnt[d], 1);
    g_edge[p] = make_int4(ei[e], ec[e], __float_as_int(ew[e]), d);
}

// ---------------------------------------------------------------------------
// Flat per-edge attention logit: e = leaky_relu(u[dst,et] + v[src,et]).
// Payload reads coalesced; u-gathers are CSR-grouped (same dst for consecutive
// slots -> L1 hits); only v-gathers are random. Done ONCE per layer.
// ---------------------------------------------------------------------------
template <int LAYER>
__global__ __launch_bounds__(256) void e_kernel() {
    int i = blockIdx.x * blockDim.x + threadIdx.x;
    if (i >= N_EDGESC) return;
    int4 pl = g_edge[i];
    int src = pl.x, et = pl.y, dst = pl.w;
    float e;
    if (LAYER == 1)
        e = g_h1[(size_t)dst * NP1 + 576 + et] + g_h1[(size_t)src * NP1 + 584 + et];
    else
        e = g_h2[(size_t)dst * NP2 + 144 + et] + g_h2[(size_t)src * NP2 + 152 + et];
    e = e >= 0.f ? e : 0.2f * e;
    g_e[i] = e;
}

// ---------------------------------------------------------------------------
// TF32 tensor-core GEMM: C[M,N] = A[M,K] @ B[K,N].
// Block tile 128x128, BK=16, 8 warps (2x4), warp tile 64x32.
// Register-prefetch pipeline: load tile t+1 global->regs while computing
// tile t from smem. cvt.rna.tf32 applied at smem store.
// ---------------------------------------------------------------------------
#define LDSW 136

template <int LAYER>
__global__ __launch_bounds__(256, 2) void gemm_tf32(const float* __restrict__ x_in) {
    constexpr int K = (LAYER == 1) ? NF : DIMS;
    constexpr int N = (LAYER == 1) ? NP1 : NP2;
    const float* __restrict__ A = (LAYER == 1) ? x_in : g_x2;
    const float* __restrict__ Bw = (LAYER == 1) ? g_W1 : g_W2;
    float* __restrict__ C        = (LAYER == 1) ? g_h1 : g_h2;

    __shared__ uint32_t As[16 * LDSW];
    __shared__ uint32_t Bs[16 * LDSW];

    int tid = threadIdx.x;
    int lane = tid & 31, wid = tid >> 5;
    int row0 = blockIdx.y * 128, col0 = blockIdx.x * 128;
    int wm = wid >> 2, wn = wid & 3;          // warp grid 2 (m) x 4 (n)
    int gq = lane >> 2, tq = lane & 3;        // fragment coords

    // load indices (each thread: 2 float4 of A, 2 float4 of B per 16-k tile)
    int ar[2], ac4[2], bk[2], bn[2];
#pragma unroll
    for (int p = 0; p < 2; p++) {
        int f = tid + p * 256;
        ar[p] = f >> 2;  ac4[p] = f & 3;      // A: 128 rows x 4 k-quads
        bk[p] = f >> 5;  bn[p]  = f & 31;     // B: 16 k x 32 n-quads
    }

    float4 pa[2], pb[2];
#pragma unroll
    for (int p = 0; p < 2; p++) {
        int gr = row0 + ar[p];
        pa[p] = (gr < N_NODES) ? *(const float4*)&A[(size_t)gr * K + ac4[p] * 4]
                               : make_float4(0.f, 0.f, 0.f, 0.f);
        pb[p] = *(const float4*)&Bw[(size_t)bk[p] * N + col0 + bn[p] * 4];
    }

    float c[4][4][4];
#pragma unroll
    for (int a = 0; a < 4; a++)
#pragma unroll
        for (int b = 0; b < 4; b++)
#pragma unroll
            for (int d = 0; d < 4; d++) c[a][b][d] = 0.f;

    for (int kt = 0; kt < K; kt += 16) {
        // store prefetched tile to smem (with tf32 conversion)
#pragma unroll
        for (int p = 0; p < 2; p++) {
            As[(ac4[p] * 4 + 0) * LDSW + ar[p]] = f2tf(pa[p].x);
            As[(ac4[p] * 4 + 1) * LDSW + ar[p]] = f2tf(pa[p].y);
            As[(ac4[p] * 4 + 2) * LDSW + ar[p]] = f2tf(pa[p].z);
            As[(ac4[p] * 4 + 3) * LDSW + ar[p]] = f2tf(pa[p].w);
            uint32_t* dst = &Bs[bk[p] * LDSW + bn[p] * 4];
            dst[0] = f2tf(pb[p].x); dst[1] = f2tf(pb[p].y);
            dst[2] = f2tf(pb[p].z); dst[3] = f2tf(pb[p].w);
        }
        __syncthreads();

        // prefetch next tile while computing this one
        if (kt + 16 < K) {
#pragma unroll
            for (int p = 0; p < 2; p++) {
                int gr = row0 + ar[p];
                pa[p] = (gr < N_NODES)
                        ? *(const float4*)&A[(size_t)gr * K + kt + 16 + ac4[p] * 4]
                        : make_float4(0.f, 0.f, 0.f, 0.f);
                pb[p] = *(const float4*)&Bw[(size_t)(kt + 16 + bk[p]) * N + col0 + bn[p] * 4];
            }
        }

#pragma unroll
        for (int k8 = 0; k8 < 16; k8 += 8) {
            uint32_t af[4][4], bf[4][2];
#pragma unroll
            for (int mi = 0; mi < 4; mi++) {
                int R = wm * 64 + mi * 16;
                af[mi][0] = As[(k8 + tq) * LDSW + R + gq];
                af[mi][1] = As[(k8 + tq) * LDSW + R + gq + 8];
                af[mi][2] = As[(k8 + tq + 4) * LDSW + R + gq];
                af[mi][3] = As[(k8 + tq + 4) * LDSW + R + gq + 8];
            }
#pragma unroll
            for (int nj = 0; nj < 4; nj++) {
                int Cb = wn * 32 + nj * 8;
                bf[nj][0] = Bs[(k8 + tq) * LDSW + Cb + gq];
                bf[nj][1] = Bs[(k8 + tq + 4) * LDSW + Cb + gq];
            }
#pragma unroll
            for (int mi = 0; mi < 4; mi++)
#pragma unroll
                for (int nj = 0; nj < 4; nj++) {
                    asm volatile(
                        "mma.sync.aligned.m16n8k8.row.col.f32.tf32.tf32.f32 "
                        "{%0,%1,%2,%3}, {%4,%5,%6,%7}, {%8,%9}, {%0,%1,%2,%3};\n"
                        : "+f"(c[mi][nj][0]), "+f"(c[mi][nj][1]),
                          "+f"(c[mi][nj][2]), "+f"(c[mi][nj][3])
                        : "r"(af[mi][0]), "r"(af[mi][1]), "r"(af[mi][2]), "r"(af[mi][3]),
                          "r"(bf[nj][0]), "r"(bf[nj][1]));
                }
        }
        __syncthreads();
    }

#pragma unroll
    for (int mi = 0; mi < 4; mi++) {
#pragma unroll
        for (int nj = 0; nj < 4; nj++) {
            int row = row0 + wm * 64 + mi * 16 + gq;
            int col = col0 + wn * 32 + nj * 8 + 2 * tq;
            if (row < N_NODES)
                *(float2*)&C[(size_t)row * N + col] = make_float2(c[mi][nj][0], c[mi][nj][1]);
            if (row + 8 < N_NODES)
                *(float2*)&C[(size_t)(row + 8) * N + col] = make_float2(c[mi][nj][2], c[mi][nj][3]);
        }
    }
}

// ---------------------------------------------------------------------------
// Edge pass layer 1: warp per destination node.
// Pass A: max over precomputed g_e (coalesced). Pass B: accumulate sum(exp)
// and sum(ew*exp*h_src) (64-dim, 2 floats/lane).
// ---------------------------------------------------------------------------
__global__ __launch_bounds__(256) void edge1_kernel(const float* __restrict__ b1) {
    int w = (blockIdx.x * blockDim.x + threadIdx.x) >> 5;
    int lane = threadIdx.x & 31;
    if (w >= N_NODES) return;
    int rb = g_rowptr[w], re = g_rowptr[w + 1];
    size_t dbase = (size_t)w * NP1;

    float m = -3.4e38f;
    for (int i = rb + lane; i < re; i += 32) m = fmaxf(m, g_e[i]);
#pragma unroll
    for (int o = 16; o > 0; o >>= 1) m = fmaxf(m, __shfl_xor_sync(0xffffffffu, m, o));

    float acc0 = 0.f, acc1 = 0.f, sum = 0.f;
    int f2 = lane * 2;
    for (int i = rb; i < re; i++) {
        int4 pl = g_edge[i];
        float ex = __expf(g_e[i] - m);
        sum += ex;
        float cc = __int_as_float(pl.z) * ex;
        float2 hv = *(const float2*)&g_h1[(size_t)pl.x * NP1 + pl.y * DIMS + f2];
        acc0 += cc * hv.x;
        acc1 += cc * hv.y;
    }
    float inv = 1.f / (sum + 1e-16f);
    float o0 = acc0 * inv + g_h1[dbase + 512 + f2]     + b1[f2];
    float o1 = acc1 * inv + g_h1[dbase + 512 + f2 + 1] + b1[f2 + 1];
    o0 = fmaxf(o0, 0.f);
    o1 = fmaxf(o1, 0.f);
    *(float2*)&g_x2[(size_t)w * DIMS + f2] = make_float2(o0, o1);
}

// ---------------------------------------------------------------------------
// Edge pass layer 2: warp per dst; halves of the warp process alternate edges
// (16-dim features). Finish with in-warp log_softmax; write both outputs.
// ---------------------------------------------------------------------------
__global__ __launch_bounds__(256) void edge2_kernel(const float* __restrict__ b2,
                                                    float* __restrict__ out,
                                                    int write_logits) {
    int d = (blockIdx.x * blockDim.x + threadIdx.x) >> 5;
    int lane = threadIdx.x & 31;
    if (d >= N_NODES) return;
    int rb = g_rowptr[d], re = g_rowptr[d + 1];
    size_t dbase = (size_t)d * NP2;

    float m = -3.4e38f;
    for (int i = rb + lane; i < re; i += 32) m = fmaxf(m, g_e[i]);
#pragma unroll
    for (int o = 16; o > 0; o >>= 1) m = fmaxf(m, __shfl_xor_sync(0xffffffffu, m, o));

    int hw = lane >> 4, f = lane & 15;
    float acc = 0.f, sum = 0.f;
    for (int i = rb + hw; i < re; i += 2) {
        int4 pl = g_edge[i];
        float ex = __expf(g_e[i] - m);
        sum += ex;
        acc += __int_as_float(pl.z) * ex * g_h2[(size_t)pl.x * NP2 + pl.y * NC + f];
    }
    acc += __shfl_xor_sync(0xffffffffu, acc, 16);
    sum += __shfl_xor_sync(0xffffffffu, sum, 16);

    float logit = acc / (sum + 1e-16f) + g_h2[dbase + 128 + f] + b2[f];

    float mx = logit;
#pragma unroll
    for (int o = 8; o > 0; o >>= 1) mx = fmaxf(mx, __shfl_xor_sync(0xffffffffu, mx, o));
    float ex = __expf(logit - mx);
    float ss = ex;
#pragma unroll
    for (int o = 8; o > 0; o >>= 1) ss += __shfl_xor_sync(0xffffffffu, ss, o);
    float ls = logit - mx - __logf(ss);

    if (lane < 16) {
        out[(size_t)d * NC + f] = ls;
        if (write_logits) out[(size_t)N_NODES * NC + (size_t)d * NC + f] = logit;
    }
}

// ---------------------------------------------------------------------------
extern "C" void kernel_launch(void* const* d_in, const int* in_sizes, int n_in,
                              void* d_out, int out_size) {
    const float* x     = (const float*)d_in[0];
    const int*   ei    = (const int*)d_in[1];
    const float* ew    = (const float*)d_in[2];
    const int*   ec    = (const int*)d_in[3];
    const float* W1    = (const float*)d_in[4];
    const float* att1  = (const float*)d_in[5];
    const float* root1 = (const float*)d_in[6];
    const float* b1    = (const float*)d_in[7];
    const float* W2    = (const float*)d_in[8];
    const float* att2  = (const float*)d_in[9];
    const float* root2 = (const float*)d_in[10];
    const float* b2    = (const float*)d_in[11];
    float* out = (float*)d_out;
    int write_logits = (out_size >= 2 * N_NODES * NC);

    // 1. fused weights + CSR build (hierarchical scan) + payload scatter
    prep_kernel<<<(NF * NP1 + DIMS * NP2 + 255) / 256, 256>>>(W1, att1, root1, W2, att2, root2);
    zero_kernel<<<(N_NODES + 255) / 256, 256>>>();
    hist_kernel<<<(N_EDGESC + 255) / 256, 256>>>(ei);
    blocksum_kernel<<<SCAN_NBLK, 256>>>();
    scanb_kernel<<<1, 128>>>();
    rowptr_kernel<<<SCAN_NBLK, 256>>>();
    scatter_kernel<<<(N_EDGESC + 255) / 256, 256>>>(ei, ew, ec);

    // 2. layer-1 fused GEMM (tf32 tensor cores): [100K,128] @ [128,640]
    {
        dim3 grid(NP1 / 128, (N_NODES + 127) / 128);
        gemm_tf32<1><<<grid, 256>>>(x);
    }
    // 3. per-edge logits, then layer-1 aggregation -> x2 (with relu)
    e_kernel<1><<<(N_EDGESC + 255) / 256, 256>>>();
    edge1_kernel<<<(N_NODES * 32 + 255) / 256, 256>>>(b1);

    // 4. layer-2 fused GEMM (tf32): [100K,64] @ [64,256]
    {
        dim3 grid(NP2 / 128, (N_NODES + 127) / 128);
        gemm_tf32<2><<<grid, 256>>>(nullptr);
    }
    // 5. per-edge logits, then layer-2 aggregation + log_softmax -> out
    e_kernel<2><<<(N_EDGESC + 255) / 256, 256>>>();
    edge2_kernel<<<(N_NODES * 32 + 255) / 256, 256>>>(b2, out, write_logits);
}

// round 5
// speedup vs baseline: 1.9856x; 1.0092x over previous
#include <cuda_runtime.h>
#include <math.h>
#include <stdint.h>

#define N_NODES 100000
#define N_EDGESC 1600000
#define NF 128
#define DIMS 64
#define NC 16
#define NREL 8
#define NP1 640   // layer1 cols: 512 rel + 64 root + 8 u(dst) + 8 v(src) + 48 pad
#define NP2 256   // layer2 cols: 128 rel + 16 root + 8 u + 8 v + 96 pad

#define SCAN_CHUNK 1024
#define SCAN_NBLK 98   // 98*1024 = 100352 >= 100000

// ---- scratch (static __device__ arrays; no allocation allowed) ----
__device__ float g_h1[(size_t)N_NODES * NP1];   // 256 MB
__device__ float g_x2[(size_t)N_NODES * DIMS];  // 25.6 MB
__device__ float g_h2[(size_t)N_NODES * NP2];   // 102 MB
__device__ float g_W1[NF * NP1];
__device__ float g_W2[DIMS * NP2];
__device__ int   g_rowptr[N_NODES + 1];
__device__ int   g_cnt[N_NODES];                // counts, then cursor
__device__ int   g_bsum[SCAN_NBLK];
__device__ int4  g_edge[N_EDGESC];              // {src, et, ew_bits, dst} CSR-ordered
__device__ float g_e[N_EDGESC];                 // leaky-relu attention logits

__device__ __forceinline__ uint32_t f2tf(float f) {
    uint32_t u;
    asm("cvt.rna.tf32.f32 %0, %1;" : "=r"(u) : "f"(f));
    return u;
}

// ---------------------------------------------------------------------------
// Weight prep: build fused weight matrices.
// ---------------------------------------------------------------------------
__global__ void prep_kernel(const float* __restrict__ W1, const float* __restrict__ att1,
                            const float* __restrict__ root1,
                            const float* __restrict__ W2, const float* __restrict__ att2,
                            const float* __restrict__ root2) {
    int i = blockIdx.x * blockDim.x + threadIdx.x;
    if (i < NF * NP1) {
        int f = i / NP1, c = i % NP1;
        float v = 0.f;
        if (c < 512) {
            int r = c >> 6, o = c & 63;
            v = W1[r * NF * DIMS + f * DIMS + o];
        } else if (c < 576) {
            v = root1[f * DIMS + (c - 512)];
        } else if (c < 584) {
            int r = c - 576; float s = 0.f;
            for (int o = 0; o < DIMS; o++) s += W1[r * NF * DIMS + f * DIMS + o] * att1[r * 2 * DIMS + o];
            v = s;
        } else if (c < 592) {
            int r = c - 584; float s = 0.f;
            for (int o = 0; o < DIMS; o++) s += W1[r * NF * DIMS + f * DIMS + o] * att1[r * 2 * DIMS + DIMS + o];
            v = s;
        }
        g_W1[i] = v;
    } else {
        int j = i - NF * NP1;
        if (j < DIMS * NP2) {
            int f = j / NP2, c = j % NP2;
            float v = 0.f;
            if (c < 128) {
                int r = c >> 4, o = c & 15;
                v = W2[r * DIMS * NC + f * NC + o];
            } else if (c < 144) {
                v = root2[f * NC + (c - 128)];
            } else if (c < 152) {
                int r = c - 144; float s = 0.f;
                for (int o = 0; o < NC; o++) s += W2[r * DIMS * NC + f * NC + o] * att2[r * 2 * NC + o];
                v = s;
            } else if (c < 160) {
                int r = c - 152; float s = 0.f;
                for (int o = 0; o < NC; o++) s += W2[r * DIMS * NC + f * NC + o] * att2[r * 2 * NC + NC + o];
                v = s;
            }
            g_W2[j] = v;
        }
    }
}

__global__ void zero_kernel() {
    int i = blockIdx.x * blockDim.x + threadIdx.x;
    if (i < N_NODES) g_cnt[i] = 0;
}

__global__ void hist_kernel(const int* __restrict__ ei) {
    int e = blockIdx.x * blockDim.x + threadIdx.x;
    if (e < N_EDGESC) atomicAdd(&g_cnt[ei[N_EDGESC + e]], 1);
}

// ---- hierarchical scan: blocksums -> scan blocksums -> per-block rescan ----
__global__ __launch_bounds__(256) void blocksum_kernel() {
    __shared__ int sh[256];
    int b = blockIdx.x, t = threadIdx.x;
    int base = b * SCAN_CHUNK + t * 4;
    int s = 0;
#pragma unroll
    for (int q = 0; q < 4; q++) {
        int i = base + q;
        if (i < N_NODES) s += g_cnt[i];
    }
    sh[t] = s; __syncthreads();
    for (int off = 128; off > 0; off >>= 1) {
        if (t < off) sh[t] += sh[t + off];
        __syncthreads();
    }
    if (t == 0) g_bsum[b] = sh[0];
}

__global__ void scanb_kernel() {
    __shared__ int sh[128];
    int t = threadIdx.x;
    int v = (t < SCAN_NBLK) ? g_bsum[t] : 0;
    sh[t] = v; __syncthreads();
    for (int off = 1; off < 128; off <<= 1) {
        int x = (t >= off) ? sh[t - off] : 0;
        __syncthreads();
        sh[t] += x;
        __syncthreads();
    }
    if (t < SCAN_NBLK) g_bsum[t] = sh[t] - v;  // exclusive
}

__global__ __launch_bounds__(256) void rowptr_kernel() {
    __shared__ int sh[256];
    int b = blockIdx.x, t = threadIdx.x;
    int base = b * SCAN_CHUNK + t * 4;
    int c[4];
#pragma unroll
    for (int q = 0; q < 4; q++) {
        int i = base + q;
        c[q] = (i < N_NODES) ? g_cnt[i] : 0;
    }
    int tot = c[0] + c[1] + c[2] + c[3];
    sh[t] = tot; __syncthreads();
    for (int off = 1; off < 256; off <<= 1) {
        int x = (t >= off) ? sh[t - off] : 0;
        __syncthreads();
        sh[t] += x;
        __syncthreads();
    }
    int off = g_bsum[b] + sh[t] - tot;  // exclusive prefix for this thread
#pragma unroll
    for (int q = 0; q < 4; q++) {
        int i = base + q;
        if (i < N_NODES) {
            g_rowptr[i] = off;
            g_cnt[i] = off;   // cursor for scatter
            off += c[q];
        }
    }
    if (b == 0 && t == 0) g_rowptr[N_NODES] = N_EDGESC;
}

// single int4 scatter per edge (1 sector instead of 3)
__global__ void scatter_kernel(const int* __restrict__ ei, const float* __restrict__ ew,
                               const int* __restrict__ ec) {
    int e = blockIdx.x * blockDim.x + threadIdx.x;
    if (e >= N_EDGESC) return;
    int d = ei[N_EDGESC + e];
    int p = atomicAdd(&g_cnt[d], 1);
    g_edge[p] = make_int4(ei[e], ec[e], __float_as_int(ew[e]), d);
}

// ---------------------------------------------------------------------------
// Flat per-edge attention logit: e = leaky_relu(u[dst,et] + v[src,et]).
// ---------------------------------------------------------------------------
template <int LAYER>
__global__ __launch_bounds__(256) void e_kernel() {
    int i = blockIdx.x * blockDim.x + threadIdx.x;
    if (i >= N_EDGESC) return;
    int4 pl = g_edge[i];
    int src = pl.x, et = pl.y, dst = pl.w;
    float e;
    if (LAYER == 1)
        e = g_h1[(size_t)dst * NP1 + 576 + et] + g_h1[(size_t)src * NP1 + 584 + et];
    else
        e = g_h2[(size_t)dst * NP2 + 144 + et] + g_h2[(size_t)src * NP2 + 152 + et];
    e = e >= 0.f ? e : 0.2f * e;
    g_e[i] = e;
}

// ---------------------------------------------------------------------------
// TF32 tensor-core GEMM: C[M,N] = A[M,K] @ B[K,N].
// Block tile 128x128, BK=16, 8 warps (2x4), warp tile 64x32.
// Double-buffered smem + register prefetch; ONE __syncthreads per k-tile.
// ---------------------------------------------------------------------------
#define LDSW 136

template <int LAYER>
__global__ __launch_bounds__(256, 2) void gemm_tf32(const float* __restrict__ x_in) {
    constexpr int K = (LAYER == 1) ? NF : DIMS;
    constexpr int N = (LAYER == 1) ? NP1 : NP2;
    constexpr int T = K / 16;
    const float* __restrict__ A = (LAYER == 1) ? x_in : g_x2;
    const float* __restrict__ Bw = (LAYER == 1) ? g_W1 : g_W2;
    float* __restrict__ C        = (LAYER == 1) ? g_h1 : g_h2;

    __shared__ uint32_t As[2][16 * LDSW];
    __shared__ uint32_t Bs[2][16 * LDSW];

    int tid = threadIdx.x;
    int lane = tid & 31, wid = tid >> 5;
    int row0 = blockIdx.y * 128, col0 = blockIdx.x * 128;
    int wm = wid >> 2, wn = wid & 3;          // warp grid 2 (m) x 4 (n)
    int gq = lane >> 2, tq = lane & 3;        // fragment coords

    // load indices (each thread: 2 float4 of A, 2 float4 of B per 16-k tile)
    int ar[2], ac4[2], bk[2], bn[2];
#pragma unroll
    for (int p = 0; p < 2; p++) {
        int f = tid + p * 256;
        ar[p] = f >> 2;  ac4[p] = f & 3;      // A: 128 rows x 4 k-quads
        bk[p] = f >> 5;  bn[p]  = f & 31;     // B: 16 k x 32 n-quads
    }

    float4 pa[2], pb[2];
#pragma unroll
    for (int p = 0; p < 2; p++) {
        int gr = row0 + ar[p];
        pa[p] = (gr < N_NODES) ? *(const float4*)&A[(size_t)gr * K + ac4[p] * 4]
                               : make_float4(0.f, 0.f, 0.f, 0.f);
        pb[p] = *(const float4*)&Bw[(size_t)bk[p] * N + col0 + bn[p] * 4];
    }
    // store tile 0 into buffer 0
#pragma unroll
    for (int p = 0; p < 2; p++) {
        As[0][(ac4[p] * 4 + 0) * LDSW + ar[p]] = f2tf(pa[p].x);
        As[0][(ac4[p] * 4 + 1) * LDSW + ar[p]] = f2tf(pa[p].y);
        As[0][(ac4[p] * 4 + 2) * LDSW + ar[p]] = f2tf(pa[p].z);
        As[0][(ac4[p] * 4 + 3) * LDSW + ar[p]] = f2tf(pa[p].w);
        uint32_t* dst = &Bs[0][bk[p] * LDSW + bn[p] * 4];
        dst[0] = f2tf(pb[p].x); dst[1] = f2tf(pb[p].y);
        dst[2] = f2tf(pb[p].z); dst[3] = f2tf(pb[p].w);
    }
    __syncthreads();

    float c[4][4][4];
#pragma unroll
    for (int a = 0; a < 4; a++)
#pragma unroll
        for (int b = 0; b < 4; b++)
#pragma unroll
            for (int d = 0; d < 4; d++) c[a][b][d] = 0.f;

#pragma unroll
    for (int t = 0; t < T; t++) {
        int cur = t & 1, nxt = cur ^ 1;
        // issue global loads for next tile (latency overlapped with mma)
        if (t + 1 < T) {
#pragma unroll
            for (int p = 0; p < 2; p++) {
                int gr = row0 + ar[p];
                pa[p] = (gr < N_NODES)
                        ? *(const float4*)&A[(size_t)gr * K + (t + 1) * 16 + ac4[p] * 4]
                        : make_float4(0.f, 0.f, 0.f, 0.f);
                pb[p] = *(const float4*)&Bw[(size_t)((t + 1) * 16 + bk[p]) * N + col0 + bn[p] * 4];
            }
        }

#pragma unroll
        for (int k8 = 0; k8 < 16; k8 += 8) {
            uint32_t af[4][4], bf[4][2];
#pragma unroll
            for (int mi = 0; mi < 4; mi++) {
                int R = wm * 64 + mi * 16;
                af[mi][0] = As[cur][(k8 + tq) * LDSW + R + gq];
                af[mi][1] = As[cur][(k8 + tq) * LDSW + R + gq + 8];
                af[mi][2] = As[cur][(k8 + tq + 4) * LDSW + R + gq];
                af[mi][3] = As[cur][(k8 + tq + 4) * LDSW + R + gq + 8];
            }
#pragma unroll
            for (int nj = 0; nj < 4; nj++) {
                int Cb = wn * 32 + nj * 8;
                bf[nj][0] = Bs[cur][(k8 + tq) * LDSW + Cb + gq];
                bf[nj][1] = Bs[cur][(k8 + tq + 4) * LDSW + Cb + gq];
            }
#pragma unroll
            for (int mi = 0; mi < 4; mi++)
#pragma unroll
                for (int nj = 0; nj < 4; nj++) {
                    asm volatile(
                        "mma.sync.aligned.m16n8k8.row.col.f32.tf32.tf32.f32 "
                        "{%0,%1,%2,%3}, {%4,%5,%6,%7}, {%8,%9}, {%0,%1,%2,%3};\n"
                        : "+f"(c[mi][nj][0]), "+f"(c[mi][nj][1]),
                          "+f"(c[mi][nj][2]), "+f"(c[mi][nj][3])
                        : "r"(af[mi][0]), "r"(af[mi][1]), "r"(af[mi][2]), "r"(af[mi][3]),
                          "r"(bf[nj][0]), "r"(bf[nj][1]));
                }
        }

        if (t + 1 < T) {
            // store next tile into the other buffer (no conflict with readers of cur)
#pragma unroll
            for (int p = 0; p < 2; p++) {
                As[nxt][(ac4[p] * 4 + 0) * LDSW + ar[p]] = f2tf(pa[p].x);
                As[nxt][(ac4[p] * 4 + 1) * LDSW + ar[p]] = f2tf(pa[p].y);
                As[nxt][(ac4[p] * 4 + 2) * LDSW + ar[p]] = f2tf(pa[p].z);
                As[nxt][(ac4[p] * 4 + 3) * LDSW + ar[p]] = f2tf(pa[p].w);
                uint32_t* dst = &Bs[nxt][bk[p] * LDSW + bn[p] * 4];
                dst[0] = f2tf(pb[p].x); dst[1] = f2tf(pb[p].y);
                dst[2] = f2tf(pb[p].z); dst[3] = f2tf(pb[p].w);
            }
            __syncthreads();
        }
    }

#pragma unroll
    for (int mi = 0; mi < 4; mi++) {
#pragma unroll
        for (int nj = 0; nj < 4; nj++) {
            int row = row0 + wm * 64 + mi * 16 + gq;
            int col = col0 + wn * 32 + nj * 8 + 2 * tq;
            if (row < N_NODES)
                *(float2*)&C[(size_t)row * N + col] = make_float2(c[mi][nj][0], c[mi][nj][1]);
            if (row + 8 < N_NODES)
                *(float2*)&C[(size_t)(row + 8) * N + col] = make_float2(c[mi][nj][2], c[mi][nj][3]);
        }
    }
}

// ---------------------------------------------------------------------------
// Edge pass layer 1: warp per destination node.
// ---------------------------------------------------------------------------
__global__ __launch_bounds__(256) void edge1_kernel(const float* __restrict__ b1) {
    int w = (blockIdx.x * blockDim.x + threadIdx.x) >> 5;
    int lane = threadIdx.x & 31;
    if (w >= N_NODES) return;
    int rb = g_rowptr[w], re = g_rowptr[w + 1];
    size_t dbase = (size_t)w * NP1;

    float m = -3.4e38f;
    for (int i = rb + lane; i < re; i += 32) m = fmaxf(m, g_e[i]);
#pragma unroll
    for (int o = 16; o > 0; o >>= 1) m = fmaxf(m, __shfl_xor_sync(0xffffffffu, m, o));

    float acc0 = 0.f, acc1 = 0.f, sum = 0.f;
    int f2 = lane * 2;
    for (int i = rb; i < re; i++) {
        int4 pl = g_edge[i];
        float ex = __expf(g_e[i] - m);
        sum += ex;
        float cc = __int_as_float(pl.z) * ex;
        float2 hv = *(const float2*)&g_h1[(size_t)pl.x * NP1 + pl.y * DIMS + f2];
        acc0 += cc * hv.x;
        acc1 += cc * hv.y;
    }
    float inv = 1.f / (sum + 1e-16f);
    float o0 = acc0 * inv + g_h1[dbase + 512 + f2]     + b1[f2];
    float o1 = acc1 * inv + g_h1[dbase + 512 + f2 + 1] + b1[f2 + 1];
    o0 = fmaxf(o0, 0.f);
    o1 = fmaxf(o1, 0.f);
    *(float2*)&g_x2[(size_t)w * DIMS + f2] = make_float2(o0, o1);
}

// ---------------------------------------------------------------------------
// Edge pass layer 2: warp per dst; in-warp log_softmax; write both outputs.
// ---------------------------------------------------------------------------
__global__ __launch_bounds__(256) void edge2_kernel(const float* __restrict__ b2,
                                                    float* __restrict__ out,
                                                    int write_logits) {
    int d = (blockIdx.x * blockDim.x + threadIdx.x) >> 5;
    int lane = threadIdx.x & 31;
    if (d >= N_NODES) return;
    int rb = g_rowptr[d], re = g_rowptr[d + 1];
    size_t dbase = (size_t)d * NP2;

    float m = -3.4e38f;
    for (int i = rb + lane; i < re; i += 32) m = fmaxf(m, g_e[i]);
#pragma unroll
    for (int o = 16; o > 0; o >>= 1) m = fmaxf(m, __shfl_xor_sync(0xffffffffu, m, o));

    int hw = lane >> 4, f = lane & 15;
    float acc = 0.f, sum = 0.f;
    for (int i = rb + hw; i < re; i += 2) {
        int4 pl = g_edge[i];
        float ex = __expf(g_e[i] - m);
        sum += ex;
        acc += __int_as_float(pl.z) * ex * g_h2[(size_t)pl.x * NP2 + pl.y * NC + f];
    }
    acc += __shfl_xor_sync(0xffffffffu, acc, 16);
    sum += __shfl_xor_sync(0xffffffffu, sum, 16);

    float logit = acc / (sum + 1e-16f) + g_h2[dbase + 128 + f] + b2[f];

    float mx = logit;
#pragma unroll
    for (int o = 8; o > 0; o >>= 1) mx = fmaxf(mx, __shfl_xor_sync(0xffffffffu, mx, o));
    float ex = __expf(logit - mx);
    float ss = ex;
#pragma unroll
    for (int o = 8; o > 0; o >>= 1) ss += __shfl_xor_sync(0xffffffffu, ss, o);
    float ls = logit - mx - __logf(ss);

    if (lane < 16) {
        out[(size_t)d * NC + f] = ls;
        if (write_logits) out[(size_t)N_NODES * NC + (size_t)d * NC + f] = logit;
    }
}

// ---------------------------------------------------------------------------
extern "C" void kernel_launch(void* const* d_in, const int* in_sizes, int n_in,
                              void* d_out, int out_size) {
    const float* x     = (const float*)d_in[0];
    const int*   ei    = (const int*)d_in[1];
    const float* ew    = (const float*)d_in[2];
    const int*   ec    = (const int*)d_in[3];
    const float* W1    = (const float*)d_in[4];
    const float* att1  = (const float*)d_in[5];
    const float* root1 = (const float*)d_in[6];
    const float* b1    = (const float*)d_in[7];
    const float* W2    = (const float*)d_in[8];
    const float* att2  = (const float*)d_in[9];
    const float* root2 = (const float*)d_in[10];
    const float* b2    = (const float*)d_in[11];
    float* out = (float*)d_out;
    int write_logits = (out_size >= 2 * N_NODES * NC);

    // Fork a side stream: CSR build runs concurrently with prep+GEMM1.
    cudaStream_t s1;
    cudaStreamCreateWithFlags(&s1, cudaStreamNonBlocking);
    cudaEvent_t evFork, evJoin;
    cudaEventCreateWithFlags(&evFork, cudaEventDisableTiming);
    cudaEventCreateWithFlags(&evJoin, cudaEventDisableTiming);

    cudaEventRecord(evFork, 0);
    cudaStreamWaitEvent(s1, evFork, 0);

    // side stream: CSR build (hierarchical scan) + payload scatter
    zero_kernel<<<(N_NODES + 255) / 256, 256, 0, s1>>>();
    hist_kernel<<<(N_EDGESC + 255) / 256, 256, 0, s1>>>(ei);
    blocksum_kernel<<<SCAN_NBLK, 256, 0, s1>>>();
    scanb_kernel<<<1, 128, 0, s1>>>();
    rowptr_kernel<<<SCAN_NBLK, 256, 0, s1>>>();
    scatter_kernel<<<(N_EDGESC + 255) / 256, 256, 0, s1>>>(ei, ew, ec);
    cudaEventRecord(evJoin, s1);

    // main stream: fused weights + layer-1 GEMM
    prep_kernel<<<(NF * NP1 + DIMS * NP2 + 255) / 256, 256>>>(W1, att1, root1, W2, att2, root2);
    {
        dim3 grid(NP1 / 128, (N_NODES + 127) / 128);
        gemm_tf32<1><<<grid, 256>>>(x);
    }

    // join: edge phase needs both g_h1 and the CSR
    cudaStreamWaitEvent(0, evJoin, 0);

    e_kernel<1><<<(N_EDGESC + 255) / 256, 256>>>();
    edge1_kernel<<<(N_NODES * 32 + 255) / 256, 256>>>(b1);

    {
        dim3 grid(NP2 / 128, (N_NODES + 127) / 128);
        gemm_tf32<2><<<grid, 256>>>(nullptr);
    }
    e_kernel<2><<<(N_EDGESC + 255) / 256, 256>>>();
    edge2_kernel<<<(N_NODES * 32 + 255) / 256, 256>>>(b2, out, write_logits);

    cudaEventDestroy(evFork);
    cudaEventDestroy(evJoin);
    cudaStreamDestroy(s1);
}

// round 6
// speedup vs baseline: 2.0243x; 1.0195x over previous
#include <cuda_runtime.h>
#include <math.h>
#include <stdint.h>

#define N_NODES 100000
#define N_EDGESC 1600000
#define NF 128
#define DIMS 64
#define NC 16
#define NREL 8
#define NP1 640   // layer1 cols: 512 rel + 64 root + 8 u(dst) + 8 v(src) + 48 pad
#define NP2 256   // layer2 cols: 128 rel + 16 root + 8 u + 8 v + 96 pad

#define SCAN_CHUNK 1024
#define SCAN_NBLK 98   // 98*1024 = 100352 >= 100000

// ---- scratch (static __device__ arrays; no allocation allowed) ----
__device__ float g_h1[(size_t)N_NODES * NP1];   // 256 MB
__device__ float g_x2[(size_t)N_NODES * DIMS];  // 25.6 MB
__device__ float g_h2[(size_t)N_NODES * NP2];   // 102 MB
__device__ float g_W1[NF * NP1];
__device__ float g_W2[DIMS * NP2];
__device__ int   g_rowptr[N_NODES + 1];
__device__ int   g_cnt[N_NODES];                // counts, then cursor
__device__ int   g_bsum[SCAN_NBLK];
__device__ int4  g_edge[N_EDGESC];              // {src, et, ew_bits, dst} CSR-ordered
__device__ float g_e[N_EDGESC];                 // leaky-relu attention logits

__device__ __forceinline__ uint32_t f2tf(float f) {
    uint32_t u;
    asm("cvt.rna.tf32.f32 %0, %1;" : "=r"(u) : "f"(f));
    return u;
}

// ---------------------------------------------------------------------------
// Weight prep: build fused weight matrices.
// ---------------------------------------------------------------------------
__global__ void prep_kernel(const float* __restrict__ W1, const float* __restrict__ att1,
                            const float* __restrict__ root1,
                            const float* __restrict__ W2, const float* __restrict__ att2,
                            const float* __restrict__ root2) {
    int i = blockIdx.x * blockDim.x + threadIdx.x;
    if (i < NF * NP1) {
        int f = i / NP1, c = i % NP1;
        float v = 0.f;
        if (c < 512) {
            int r = c >> 6, o = c & 63;
            v = W1[r * NF * DIMS + f * DIMS + o];
        } else if (c < 576) {
            v = root1[f * DIMS + (c - 512)];
        } else if (c < 584) {
            int r = c - 576; float s = 0.f;
            for (int o = 0; o < DIMS; o++) s += W1[r * NF * DIMS + f * DIMS + o] * att1[r * 2 * DIMS + o];
            v = s;
        } else if (c < 592) {
            int r = c - 584; float s = 0.f;
            for (int o = 0; o < DIMS; o++) s += W1[r * NF * DIMS + f * DIMS + o] * att1[r * 2 * DIMS + DIMS + o];
            v = s;
        }
        g_W1[i] = v;
    } else {
        int j = i - NF * NP1;
        if (j < DIMS * NP2) {
            int f = j / NP2, c = j % NP2;
            float v = 0.f;
            if (c < 128) {
                int r = c >> 4, o = c & 15;
                v = W2[r * DIMS * NC + f * NC + o];
            } else if (c < 144) {
                v = root2[f * NC + (c - 128)];
            } else if (c < 152) {
                int r = c - 144; float s = 0.f;
                for (int o = 0; o < NC; o++) s += W2[r * DIMS * NC + f * NC + o] * att2[r * 2 * NC + o];
                v = s;
            } else if (c < 160) {
                int r = c - 152; float s = 0.f;
                for (int o = 0; o < NC; o++) s += W2[r * DIMS * NC + f * NC + o] * att2[r * 2 * NC + NC + o];
                v = s;
            }
            g_W2[j] = v;
        }
    }
}

__global__ void zero_kernel() {
    int i = blockIdx.x * blockDim.x + threadIdx.x;
    if (i < N_NODES) g_cnt[i] = 0;
}

__global__ void hist_kernel(const int* __restrict__ ei) {
    int e = blockIdx.x * blockDim.x + threadIdx.x;
    if (e < N_EDGESC) atomicAdd(&g_cnt[ei[N_EDGESC + e]], 1);
}

// ---- hierarchical scan: blocksums -> scan blocksums -> per-block rescan ----
__global__ __launch_bounds__(256) void blocksum_kernel() {
    __shared__ int sh[256];
    int b = blockIdx.x, t = threadIdx.x;
    int base = b * SCAN_CHUNK + t * 4;
    int s = 0;
#pragma unroll
    for (int q = 0; q < 4; q++) {
        int i = base + q;
        if (i < N_NODES) s += g_cnt[i];
    }
    sh[t] = s; __syncthreads();
    for (int off = 128; off > 0; off >>= 1) {
        if (t < off) sh[t] += sh[t + off];
        __syncthreads();
    }
    if (t == 0) g_bsum[b] = sh[0];
}

__global__ void scanb_kernel() {
    __shared__ int sh[128];
    int t = threadIdx.x;
    int v = (t < SCAN_NBLK) ? g_bsum[t] : 0;
    sh[t] = v; __syncthreads();
    for (int off = 1; off < 128; off <<= 1) {
        int x = (t >= off) ? sh[t - off] : 0;
        __syncthreads();
        sh[t] += x;
        __syncthreads();
    }
    if (t < SCAN_NBLK) g_bsum[t] = sh[t] - v;  // exclusive
}

__global__ __launch_bounds__(256) void rowptr_kernel() {
    __shared__ int sh[256];
    int b = blockIdx.x, t = threadIdx.x;
    int base = b * SCAN_CHUNK + t * 4;
    int c[4];
#pragma unroll
    for (int q = 0; q < 4; q++) {
        int i = base + q;
        c[q] = (i < N_NODES) ? g_cnt[i] : 0;
    }
    int tot = c[0] + c[1] + c[2] + c[3];
    sh[t] = tot; __syncthreads();
    for (int off = 1; off < 256; off <<= 1) {
        int x = (t >= off) ? sh[t - off] : 0;
        __syncthreads();
        sh[t] += x;
        __syncthreads();
    }
    int off = g_bsum[b] + sh[t] - tot;  // exclusive prefix for this thread
#pragma unroll
    for (int q = 0; q < 4; q++) {
        int i = base + q;
        if (i < N_NODES) {
            g_rowptr[i] = off;
            g_cnt[i] = off;   // cursor for scatter
            off += c[q];
        }
    }
    if (b == 0 && t == 0) g_rowptr[N_NODES] = N_EDGESC;
}

// single int4 scatter per edge (1 sector instead of 3)
__global__ void scatter_kernel(const int* __restrict__ ei, const float* __restrict__ ew,
                               const int* __restrict__ ec) {
    int e = blockIdx.x * blockDim.x + threadIdx.x;
    if (e >= N_EDGESC) return;
    int d = ei[N_EDGESC + e];
    int p = atomicAdd(&g_cnt[d], 1);
    g_edge[p] = make_int4(ei[e], ec[e], __float_as_int(ew[e]), d);
}

// ---------------------------------------------------------------------------
// Flat per-edge attention logit: e = leaky_relu(u[dst,et] + v[src,et]).
// ---------------------------------------------------------------------------
template <int LAYER>
__global__ __launch_bounds__(256) void e_kernel() {
    int i = blockIdx.x * blockDim.x + threadIdx.x;
    if (i >= N_EDGESC) return;
    int4 pl = g_edge[i];
    int src = pl.x, et = pl.y, dst = pl.w;
    float e;
    if (LAYER == 1)
        e = g_h1[(size_t)dst * NP1 + 576 + et] + g_h1[(size_t)src * NP1 + 584 + et];
    else
        e = g_h2[(size_t)dst * NP2 + 144 + et] + g_h2[(size_t)src * NP2 + 152 + et];
    e = e >= 0.f ? e : 0.2f * e;
    g_e[i] = e;
}

// ---------------------------------------------------------------------------
// TF32 tensor-core GEMM: C[M,N] = A[M,K] @ B[K,N].
// Block tile 128x128, BK=16, 8 warps (2x4), warp tile 64x32.
// Double-buffered smem + register prefetch; ONE __syncthreads per k-tile.
// ---------------------------------------------------------------------------
#define LDSW 136

template <int LAYER>
__global__ __launch_bounds__(256, 2) void gemm_tf32(const float* __restrict__ x_in) {
    constexpr int K = (LAYER == 1) ? NF : DIMS;
    constexpr int N = (LAYER == 1) ? NP1 : NP2;
    constexpr int T = K / 16;
    constexpr int NUSE = (LAYER == 1) ? 592 : 160;   // cols actually consumed downstream
    const float* __restrict__ A = (LAYER == 1) ? x_in : g_x2;
    const float* __restrict__ Bw = (LAYER == 1) ? g_W1 : g_W2;
    float* __restrict__ C        = (LAYER == 1) ? g_h1 : g_h2;

    __shared__ uint32_t As[2][16 * LDSW];
    __shared__ uint32_t Bs[2][16 * LDSW];

    int tid = threadIdx.x;
    int lane = tid & 31, wid = tid >> 5;
    int row0 = blockIdx.y * 128, col0 = blockIdx.x * 128;
    int wm = wid >> 2, wn = wid & 3;          // warp grid 2 (m) x 4 (n)
    int gq = lane >> 2, tq = lane & 3;        // fragment coords

    int ar[2], ac4[2], bk[2], bn[2];
#pragma unroll
    for (int p = 0; p < 2; p++) {
        int f = tid + p * 256;
        ar[p] = f >> 2;  ac4[p] = f & 3;      // A: 128 rows x 4 k-quads
        bk[p] = f >> 5;  bn[p]  = f & 31;     // B: 16 k x 32 n-quads
    }

    float4 pa[2], pb[2];
#pragma unroll
    for (int p = 0; p < 2; p++) {
        int gr = row0 + ar[p];
        pa[p] = (gr < N_NODES) ? *(const float4*)&A[(size_t)gr * K + ac4[p] * 4]
                               : make_float4(0.f, 0.f, 0.f, 0.f);
        pb[p] = *(const float4*)&Bw[(size_t)bk[p] * N + col0 + bn[p] * 4];
    }
#pragma unroll
    for (int p = 0; p < 2; p++) {
        As[0][(ac4[p] * 4 + 0) * LDSW + ar[p]] = f2tf(pa[p].x);
        As[0][(ac4[p] * 4 + 1) * LDSW + ar[p]] = f2tf(pa[p].y);
        As[0][(ac4[p] * 4 + 2) * LDSW + ar[p]] = f2tf(pa[p].z);
        As[0][(ac4[p] * 4 + 3) * LDSW + ar[p]] = f2tf(pa[p].w);
        uint32_t* dst = &Bs[0][bk[p] * LDSW + bn[p] * 4];
        dst[0] = f2tf(pb[p].x); dst[1] = f2tf(pb[p].y);
        dst[2] = f2tf(pb[p].z); dst[3] = f2tf(pb[p].w);
    }
    __syncthreads();

    float c[4][4][4];
#pragma unroll
    for (int a = 0; a < 4; a++)
#pragma unroll
        for (int b = 0; b < 4; b++)
#pragma unroll
            for (int d = 0; d < 4; d++) c[a][b][d] = 0.f;

#pragma unroll
    for (int t = 0; t < T; t++) {
        int cur = t & 1, nxt = cur ^ 1;
        if (t + 1 < T) {
#pragma unroll
            for (int p = 0; p < 2; p++) {
                int gr = row0 + ar[p];
                pa[p] = (gr < N_NODES)
                        ? *(const float4*)&A[(size_t)gr * K + (t + 1) * 16 + ac4[p] * 4]
                        : make_float4(0.f, 0.f, 0.f, 0.f);
                pb[p] = *(const float4*)&Bw[(size_t)((t + 1) * 16 + bk[p]) * N + col0 + bn[p] * 4];
            }
        }

#pragma unroll
        for (int k8 = 0; k8 < 16; k8 += 8) {
            uint32_t af[4][4], bf[4][2];
#pragma unroll
            for (int mi = 0; mi < 4; mi++) {
                int R = wm * 64 + mi * 16;
                af[mi][0] = As[cur][(k8 + tq) * LDSW + R + gq];
                af[mi][1] = As[cur][(k8 + tq) * LDSW + R + gq + 8];
                af[mi][2] = As[cur][(k8 + tq + 4) * LDSW + R + gq];
                af[mi][3] = As[cur][(k8 + tq + 4) * LDSW + R + gq + 8];
            }
#pragma unroll
            for (int nj = 0; nj < 4; nj++) {
                int Cb = wn * 32 + nj * 8;
                bf[nj][0] = Bs[cur][(k8 + tq) * LDSW + Cb + gq];
                bf[nj][1] = Bs[cur][(k8 + tq + 4) * LDSW + Cb + gq];
            }
#pragma unroll
            for (int mi = 0; mi < 4; mi++)
#pragma unroll
                for (int nj = 0; nj < 4; nj++) {
                    asm volatile(
                        "mma.sync.aligned.m16n8k8.row.col.f32.tf32.tf32.f32 "
                        "{%0,%1,%2,%3}, {%4,%5,%6,%7}, {%8,%9}, {%0,%1,%2,%3};\n"
                        : "+f"(c[mi][nj][0]), "+f"(c[mi][nj][1]),
                          "+f"(c[mi][nj][2]), "+f"(c[mi][nj][3])
                        : "r"(af[mi][0]), "r"(af[mi][1]), "r"(af[mi][2]), "r"(af[mi][3]),
                          "r"(bf[nj][0]), "r"(bf[nj][1]));
                }
        }

        if (t + 1 < T) {
#pragma unroll
            for (int p = 0; p < 2; p++) {
                As[nxt][(ac4[p] * 4 + 0) * LDSW + ar[p]] = f2tf(pa[p].x);
                As[nxt][(ac4[p] * 4 + 1) * LDSW + ar[p]] = f2tf(pa[p].y);
                As[nxt][(ac4[p] * 4 + 2) * LDSW + ar[p]] = f2tf(pa[p].z);
                As[nxt][(ac4[p] * 4 + 3) * LDSW + ar[p]] = f2tf(pa[p].w);
                uint32_t* dst = &Bs[nxt][bk[p] * LDSW + bn[p] * 4];
                dst[0] = f2tf(pb[p].x); dst[1] = f2tf(pb[p].y);
                dst[2] = f2tf(pb[p].z); dst[3] = f2tf(pb[p].w);
            }
            __syncthreads();
        }
    }

#pragma unroll
    for (int mi = 0; mi < 4; mi++) {
#pragma unroll
        for (int nj = 0; nj < 4; nj++) {
            int row = row0 + wm * 64 + mi * 16 + gq;
            int col = col0 + wn * 32 + nj * 8 + 2 * tq;
            if (col >= NUSE) continue;   // skip pad columns nobody reads
            if (row < N_NODES)
                *(float2*)&C[(size_t)row * N + col] = make_float2(c[mi][nj][0], c[mi][nj][1]);
            if (row + 8 < N_NODES)
                *(float2*)&C[(size_t)(row + 8) * N + col] = make_float2(c[mi][nj][2], c[mi][nj][3]);
        }
    }
}

// ---------------------------------------------------------------------------
// Edge pass layer 1: warp per destination node. Unrolled x2 sum-pass:
// all loads for two edges issued before their FMAs (MLP ~2-3).
// ---------------------------------------------------------------------------
__global__ __launch_bounds__(256) void edge1_kernel(const float* __restrict__ b1) {
    int w = (blockIdx.x * blockDim.x + threadIdx.x) >> 5;
    int lane = threadIdx.x & 31;
    if (w >= N_NODES) return;
    int rb = g_rowptr[w], re = g_rowptr[w + 1];
    size_t dbase = (size_t)w * NP1;

    float m = -3.4e38f;
    for (int i = rb + lane; i < re; i += 32) m = fmaxf(m, g_e[i]);
#pragma unroll
    for (int o = 16; o > 0; o >>= 1) m = fmaxf(m, __shfl_xor_sync(0xffffffffu, m, o));

    float acc0 = 0.f, acc1 = 0.f, sum = 0.f;
    int f2 = lane * 2;
    int i = rb;
    for (; i + 2 <= re; i += 2) {
        int4 pl0 = g_edge[i];
        int4 pl1 = g_edge[i + 1];
        float e0 = g_e[i], e1 = g_e[i + 1];
        float2 hv0 = *(const float2*)&g_h1[(size_t)pl0.x * NP1 + pl0.y * DIMS + f2];
        float2 hv1 = *(const float2*)&g_h1[(size_t)pl1.x * NP1 + pl1.y * DIMS + f2];
        float ex0 = __expf(e0 - m);
        float ex1 = __expf(e1 - m);
        sum += ex0 + ex1;
        float c0 = __int_as_float(pl0.z) * ex0;
        float c1 = __int_as_float(pl1.z) * ex1;
        acc0 += c0 * hv0.x + c1 * hv1.x;
        acc1 += c0 * hv0.y + c1 * hv1.y;
    }
    if (i < re) {
        int4 pl = g_edge[i];
        float ex = __expf(g_e[i] - m);
        sum += ex;
        float cc = __int_as_float(pl.z) * ex;
        float2 hv = *(const float2*)&g_h1[(size_t)pl.x * NP1 + pl.y * DIMS + f2];
        acc0 += cc * hv.x;
        acc1 += cc * hv.y;
    }
    float inv = 1.f / (sum + 1e-16f);
    float o0 = acc0 * inv + g_h1[dbase + 512 + f2]     + b1[f2];
    float o1 = acc1 * inv + g_h1[dbase + 512 + f2 + 1] + b1[f2 + 1];
    o0 = fmaxf(o0, 0.f);
    o1 = fmaxf(o1, 0.f);
    *(float2*)&g_x2[(size_t)w * DIMS + f2] = make_float2(o0, o1);
}

// ---------------------------------------------------------------------------
// Edge pass layer 2: warp per dst; half-warps alternate edges; unrolled x2.
// ---------------------------------------------------------------------------
__global__ __launch_bounds__(256) void edge2_kernel(const float* __restrict__ b2,
                                                    float* __restrict__ out,
                                                    int write_logits) {
    int d = (blockIdx.x * blockDim.x + threadIdx.x) >> 5;
    int lane = threadIdx.x & 31;
    if (d >= N_NODES) return;
    int rb = g_rowptr[d], re = g_rowptr[d + 1];
    size_t dbase = (size_t)d * NP2;

    float m = -3.4e38f;
    for (int i = rb + lane; i < re; i += 32) m = fmaxf(m, g_e[i]);
#pragma unroll
    for (int o = 16; o > 0; o >>= 1) m = fmaxf(m, __shfl_xor_sync(0xffffffffu, m, o));

    int hw = lane >> 4, f = lane & 15;
    float acc = 0.f, sum = 0.f;
    int i = rb + hw;
    for (; i + 2 < re; i += 4) {
        int4 pl0 = g_edge[i];
        int4 pl1 = g_edge[i + 2];
        float e0 = g_e[i], e1 = g_e[i + 2];
        float h0 = g_h2[(size_t)pl0.x * NP2 + pl0.y * NC + f];
        float h1 = g_h2[(size_t)pl1.x * NP2 + pl1.y * NC + f];
        float ex0 = __expf(e0 - m);
        float ex1 = __expf(e1 - m);
        sum += ex0 + ex1;
        acc += __int_as_float(pl0.z) * ex0 * h0 + __int_as_float(pl1.z) * ex1 * h1;
    }
    if (i < re) {
        int4 pl = g_edge[i];
        float ex = __expf(g_e[i] - m);
        sum += ex;
        acc += __int_as_float(pl.z) * ex * g_h2[(size_t)pl.x * NP2 + pl.y * NC + f];
    }
    acc += __shfl_xor_sync(0xffffffffu, acc, 16);
    sum += __shfl_xor_sync(0xffffffffu, sum, 16);

    float logit = acc / (sum + 1e-16f) + g_h2[dbase + 128 + f] + b2[f];

    float mx = logit;
#pragma unroll
    for (int o = 8; o > 0; o >>= 1) mx = fmaxf(mx, __shfl_xor_sync(0xffffffffu, mx, o));
    float ex = __expf(logit - mx);
    float ss = ex;
#pragma unroll
    for (int o = 8; o > 0; o >>= 1) ss += __shfl_xor_sync(0xffffffffu, ss, o);
    float ls = logit - mx - __logf(ss);

    if (lane < 16) {
        out[(size_t)d * NC + f] = ls;
        if (write_logits) out[(size_t)N_NODES * NC + (size_t)d * NC + f] = logit;
    }
}

// ---------------------------------------------------------------------------
extern "C" void kernel_launch(void* const* d_in, const int* in_sizes, int n_in,
                              void* d_out, int out_size) {
    const float* x     = (const float*)d_in[0];
    const int*   ei    = (const int*)d_in[1];
    const float* ew    = (const float*)d_in[2];
    const int*   ec    = (const int*)d_in[3];
    const float* W1    = (const float*)d_in[4];
    const float* att1  = (const float*)d_in[5];
    const float* root1 = (const float*)d_in[6];
    const float* b1    = (const float*)d_in[7];
    const float* W2    = (const float*)d_in[8];
    const float* att2  = (const float*)d_in[9];
    const float* root2 = (const float*)d_in[10];
    const float* b2    = (const float*)d_in[11];
    float* out = (float*)d_out;
    int write_logits = (out_size >= 2 * N_NODES * NC);

    cudaStream_t s1;
    cudaStreamCreateWithFlags(&s1, cudaStreamNonBlocking);
    cudaEvent_t evFork, evJoin;
    cudaEventCreateWithFlags(&evFork, cudaEventDisableTiming);
    cudaEventCreateWithFlags(&evJoin, cudaEventDisableTiming);

    cudaEventRecord(evFork, 0);
    cudaStreamWaitEvent(s1, evFork, 0);

    // Issue order matters for ncu (-s lands on 4th kernel): zero(1), hist(2),
    // prep(3), gemm1(4) <- profiled next round.
    zero_kernel<<<(N_NODES + 255) / 256, 256, 0, s1>>>();
    hist_kernel<<<(N_EDGESC + 255) / 256, 256, 0, s1>>>(ei);

    prep_kernel<<<(NF * NP1 + DIMS * NP2 + 255) / 256, 256>>>(W1, att1, root1, W2, att2, root2);
    {
        dim3 grid(NP1 / 128, (N_NODES + 127) / 128);
        gemm_tf32<1><<<grid, 256>>>(x);
    }

    // rest of CSR build on the side stream (concurrent with gemm1)
    blocksum_kernel<<<SCAN_NBLK, 256, 0, s1>>>();
    scanb_kernel<<<1, 128, 0, s1>>>();
    rowptr_kernel<<<SCAN_NBLK, 256, 0, s1>>>();
    scatter_kernel<<<(N_EDGESC + 255) / 256, 256, 0, s1>>>(ei, ew, ec);
    cudaEventRecord(evJoin, s1);

    // join: edge phase needs both g_h1 and the CSR
    cudaStreamWaitEvent(0, evJoin, 0);

    e_kernel<1><<<(N_EDGESC + 255) / 256, 256>>>();
    edge1_kernel<<<(N_NODES * 32 + 255) / 256, 256>>>(b1);

    {
        dim3 grid(NP2 / 128, (N_NODES + 127) / 128);
        gemm_tf32<2><<<grid, 256>>>(nullptr);
    }
    e_kernel<2><<<(N_EDGESC + 255) / 256, 256>>>();
    edge2_kernel<<<(N_NODES * 32 + 255) / 256, 256>>>(b2, out, write_logits);

    cudaEventDestroy(evFork);
    cudaEventDestroy(evJoin);
    cudaStreamDestroy(s1);
}